// round 1
// baseline (speedup 1.0000x reference)
#include <cuda_runtime.h>
#include <math.h>

#define BATCH 16
#define NSEQ  200
#define DDIM  2048
#define HDIM  2048
#define MTOT  (BATCH*NSEQ)          // 3200

// ---------------- scratch (device globals: allocation-guard safe) ----------
__device__ float g_q1[BATCH*NSEQ*HDIM];      // lq, then lq+param
__device__ float g_q2[BATCH*NSEQ*HDIM];      // lloc, then lq+lloc
__device__ float g_lk[BATCH*NSEQ*HDIM];
__device__ float g_kloc[BATCH*NSEQ*HDIM];
__device__ float g_lv[BATCH*NSEQ*HDIM];
__device__ float g_scores[BATCH*NSEQ*NSEQ];

// ---------------- projection GEMM: C[M=3200,N=2048] = A[M,K=2048] @ W[K,N] + bias
// 128x128 tile, BK=16, 256 threads, 8x8 per-thread microtile.
__global__ __launch_bounds__(256) void gemm_proj(const float* __restrict__ A,
                                                 const float* __restrict__ W,
                                                 const float* __restrict__ bias,
                                                 float* __restrict__ C)
{
    __shared__ float As[16][128];
    __shared__ float Bs[16][128];
    const int bm = blockIdx.y * 128;
    const int bn = blockIdx.x * 128;
    const int tid = threadIdx.x;
    const int ty = tid >> 4;          // 0..15
    const int tx = tid & 15;          // 0..15

    float acc[8][8];
#pragma unroll
    for (int i = 0; i < 8; i++)
#pragma unroll
        for (int j = 0; j < 8; j++) acc[i][j] = 0.f;

    for (int k0 = 0; k0 < DDIM; k0 += 16) {
        // A tile: 128 rows x 16 cols  (512 float4, 2 per thread), stored transposed
#pragma unroll
        for (int it = 0; it < 2; it++) {
            int f = tid + it * 256;
            int row = f >> 2;
            int c4  = (f & 3) << 2;
            float4 v = *(const float4*)(A + (size_t)(bm + row) * DDIM + k0 + c4);
            As[c4 + 0][row] = v.x;
            As[c4 + 1][row] = v.y;
            As[c4 + 2][row] = v.z;
            As[c4 + 3][row] = v.w;
        }
        // W tile: 16 rows x 128 cols (512 float4, 2 per thread)
#pragma unroll
        for (int it = 0; it < 2; it++) {
            int f = tid + it * 256;
            int row = f >> 5;
            int c4  = (f & 31) << 2;
            *(float4*)(&Bs[row][c4]) =
                *(const float4*)(W + (size_t)(k0 + row) * HDIM + bn + c4);
        }
        __syncthreads();

#pragma unroll
        for (int kk = 0; kk < 16; kk++) {
            float a[8], b[8];
#pragma unroll
            for (int i = 0; i < 8; i++) a[i] = As[kk][ty * 8 + i];
#pragma unroll
            for (int j = 0; j < 8; j++) b[j] = Bs[kk][tx * 8 + j];
#pragma unroll
            for (int i = 0; i < 8; i++)
#pragma unroll
                for (int j = 0; j < 8; j++)
                    acc[i][j] = fmaf(a[i], b[j], acc[i][j]);
        }
        __syncthreads();
    }

    float bb[8];
#pragma unroll
    for (int j = 0; j < 8; j++) bb[j] = bias[bn + tx * 8 + j];

#pragma unroll
    for (int i = 0; i < 8; i++) {
        size_t off = (size_t)(bm + ty * 8 + i) * HDIM + bn + tx * 8;
        float4 v0 = make_float4(acc[i][0] + bb[0], acc[i][1] + bb[1],
                                acc[i][2] + bb[2], acc[i][3] + bb[3]);
        float4 v1 = make_float4(acc[i][4] + bb[4], acc[i][5] + bb[5],
                                acc[i][6] + bb[6], acc[i][7] + bb[7]);
        *(float4*)(C + off)     = v0;
        *(float4*)(C + off + 4) = v1;
    }
}

// ---------------- elementwise: q1 = lq + param ; q2 = lq + lloc ------------
__global__ void add_kernel(const float* __restrict__ param)
{
    size_t i = (size_t)blockIdx.x * 256 + threadIdx.x;
    if (i < (size_t)BATCH * NSEQ * HDIM) {
        float lq = g_q1[i];
        float ll = g_q2[i];
        g_q1[i] = lq + param[i];
        g_q2[i] = lq + ll;
    }
}

// ---------------- scores: s[b,n,m] = q1[b,n,:].lk[b,m,:] + q2[b,n,:].kloc[b,m,:]
// 64x64 tile over (n,m), BK=16 over H, 256 threads, 4x4 per-thread.
__global__ __launch_bounds__(256) void scores_kernel()
{
    __shared__ float Qa[16][64], Qb[16][64], Ka[16][64], Kb[16][64];
    const int b  = blockIdx.z;
    const int n0 = blockIdx.y * 64;
    const int m0 = blockIdx.x * 64;
    const size_t bo = (size_t)b * NSEQ * HDIM;
    const float* q1 = g_q1 + bo;
    const float* q2 = g_q2 + bo;
    const float* lk = g_lk + bo;
    const float* kl = g_kloc + bo;

    const int tid = threadIdx.x;
    const int row = tid >> 2;
    const int c4  = (tid & 3) << 2;
    const int ty = tid >> 4, tx = tid & 15;

    float acc[4][4];
#pragma unroll
    for (int i = 0; i < 4; i++)
#pragma unroll
        for (int j = 0; j < 4; j++) acc[i][j] = 0.f;

    for (int k0 = 0; k0 < HDIM; k0 += 16) {
        float4 v;
        // Q tiles (rows n0+row)
        if (n0 + row < NSEQ) v = *(const float4*)(q1 + (size_t)(n0 + row) * HDIM + k0 + c4);
        else                 v = make_float4(0, 0, 0, 0);
        Qa[c4 + 0][row] = v.x; Qa[c4 + 1][row] = v.y; Qa[c4 + 2][row] = v.z; Qa[c4 + 3][row] = v.w;
        if (n0 + row < NSEQ) v = *(const float4*)(q2 + (size_t)(n0 + row) * HDIM + k0 + c4);
        else                 v = make_float4(0, 0, 0, 0);
        Qb[c4 + 0][row] = v.x; Qb[c4 + 1][row] = v.y; Qb[c4 + 2][row] = v.z; Qb[c4 + 3][row] = v.w;
        // K tiles (rows m0+row)
        if (m0 + row < NSEQ) v = *(const float4*)(lk + (size_t)(m0 + row) * HDIM + k0 + c4);
        else                 v = make_float4(0, 0, 0, 0);
        Ka[c4 + 0][row] = v.x; Ka[c4 + 1][row] = v.y; Ka[c4 + 2][row] = v.z; Ka[c4 + 3][row] = v.w;
        if (m0 + row < NSEQ) v = *(const float4*)(kl + (size_t)(m0 + row) * HDIM + k0 + c4);
        else                 v = make_float4(0, 0, 0, 0);
        Kb[c4 + 0][row] = v.x; Kb[c4 + 1][row] = v.y; Kb[c4 + 2][row] = v.z; Kb[c4 + 3][row] = v.w;
        __syncthreads();

#pragma unroll
        for (int kk = 0; kk < 16; kk++) {
            float a1[4], a2[4], b1[4], b2[4];
#pragma unroll
            for (int i = 0; i < 4; i++) { a1[i] = Qa[kk][ty * 4 + i]; a2[i] = Qb[kk][ty * 4 + i]; }
#pragma unroll
            for (int j = 0; j < 4; j++) { b1[j] = Ka[kk][tx * 4 + j]; b2[j] = Kb[kk][tx * 4 + j]; }
#pragma unroll
            for (int i = 0; i < 4; i++)
#pragma unroll
                for (int j = 0; j < 4; j++)
                    acc[i][j] = fmaf(a1[i], b1[j], fmaf(a2[i], b2[j], acc[i][j]));
        }
        __syncthreads();
    }

    float* sc = g_scores + (size_t)b * NSEQ * NSEQ;
#pragma unroll
    for (int i = 0; i < 4; i++) {
        int n = n0 + ty * 4 + i;
        if (n >= NSEQ) continue;
#pragma unroll
        for (int j = 0; j < 4; j++) {
            int m = m0 + tx * 4 + j;
            if (m < NSEQ) sc[(size_t)n * NSEQ + m] = acc[i][j];
        }
    }
}

// ---------------- softmax over m (length 200), scaled by 1/sqrt(H) --------
__global__ __launch_bounds__(256) void softmax_kernel()
{
    const int row = blockIdx.x;                // 0..3199
    float* s = g_scores + (size_t)row * NSEQ;
    const int tid = threadIdx.x;
    __shared__ float red[8];

    float v = (tid < NSEQ) ? s[tid] : -3.0e38f;
    // block max
#pragma unroll
    for (int o = 16; o; o >>= 1) v = fmaxf(v, __shfl_xor_sync(0xffffffffu, v, o));
    if ((tid & 31) == 0) red[tid >> 5] = v;
    __syncthreads();
    float vmax = red[0];
#pragma unroll
    for (int w = 1; w < 8; w++) vmax = fmaxf(vmax, red[w]);

    const float scale = 0.02209708691207961f;  // 1/sqrt(2048)
    float e = (tid < NSEQ) ? __expf((((tid < NSEQ) ? s[tid] : 0.f) - vmax) * scale) : 0.f;
    float sum = e;
#pragma unroll
    for (int o = 16; o; o >>= 1) sum += __shfl_xor_sync(0xffffffffu, sum, o);
    __syncthreads();
    if ((tid & 31) == 0) red[tid >> 5] = sum;
    __syncthreads();
    float tot = 0.f;
#pragma unroll
    for (int w = 0; w < 8; w++) tot += red[w];

    if (tid < NSEQ) s[tid] = e / tot;
}

// ---------------- output: out[b,n,o] = sum_m attn[b,n,m] * lv[b,m,o] ------
// 64(n) x 64(o) tile, BK=16 over m (200), 256 threads, 4x4 per-thread.
__global__ __launch_bounds__(256) void out_kernel(float* __restrict__ out)
{
    __shared__ float Ps[16][64];   // [m][n]
    __shared__ float Vs[16][64];   // [m][o]
    const int b  = blockIdx.z;
    const int n0 = blockIdx.y * 64;
    const int o0 = blockIdx.x * 64;
    const float* attn = g_scores + (size_t)b * NSEQ * NSEQ;
    const float* lv   = g_lv     + (size_t)b * NSEQ * HDIM;

    const int tid = threadIdx.x;
    const int ty = tid >> 4, tx = tid & 15;

    float acc[4][4];
#pragma unroll
    for (int i = 0; i < 4; i++)
#pragma unroll
        for (int j = 0; j < 4; j++) acc[i][j] = 0.f;

    for (int m0 = 0; m0 < NSEQ; m0 += 16) {
        // attn tile: 64 n-rows x 16 m-cols, transposed into Ps[m][n]
        {
            int row = tid >> 2;
            int c4  = (tid & 3) << 2;
            float4 v = make_float4(0, 0, 0, 0);
            int n = n0 + row;
            if (n < NSEQ) {
                int m = m0 + c4;
                if (m + 3 < NSEQ) {
                    v = *(const float4*)(attn + (size_t)n * NSEQ + m);
                } else {
                    const float* p = attn + (size_t)n * NSEQ;
                    v.x = (m + 0 < NSEQ) ? p[m + 0] : 0.f;
                    v.y = (m + 1 < NSEQ) ? p[m + 1] : 0.f;
                    v.z = (m + 2 < NSEQ) ? p[m + 2] : 0.f;
                    v.w = (m + 3 < NSEQ) ? p[m + 3] : 0.f;
                }
            }
            Ps[c4 + 0][row] = v.x; Ps[c4 + 1][row] = v.y;
            Ps[c4 + 2][row] = v.z; Ps[c4 + 3][row] = v.w;
        }
        // lv tile: 16 m-rows x 64 o-cols
        {
            int row = tid >> 4;             // 0..15
            int c4  = (tid & 15) << 2;      // 0..60
            float4 v = make_float4(0, 0, 0, 0);
            int m = m0 + row;
            if (m < NSEQ)
                v = *(const float4*)(lv + (size_t)m * HDIM + o0 + c4);
            *(float4*)(&Vs[row][c4]) = v;
        }
        __syncthreads();

#pragma unroll
        for (int kk = 0; kk < 16; kk++) {
            float a[4], bfr[4];
#pragma unroll
            for (int i = 0; i < 4; i++) a[i] = Ps[kk][ty * 4 + i];
#pragma unroll
            for (int j = 0; j < 4; j++) bfr[j] = Vs[kk][tx * 4 + j];
#pragma unroll
            for (int i = 0; i < 4; i++)
#pragma unroll
                for (int j = 0; j < 4; j++)
                    acc[i][j] = fmaf(a[i], bfr[j], acc[i][j]);
        }
        __syncthreads();
    }

#pragma unroll
    for (int i = 0; i < 4; i++) {
        int n = n0 + ty * 4 + i;
        if (n >= NSEQ) continue;
        size_t off = ((size_t)b * NSEQ + n) * HDIM + o0 + tx * 4;
        float4 v = make_float4(acc[i][0], acc[i][1], acc[i][2], acc[i][3]);
        *(float4*)(out + off) = v;
    }
}

// ---------------------------------------------------------------------------
extern "C" void kernel_launch(void* const* d_in, const int* in_sizes, int n_in,
                              void* d_out, int out_size)
{
    const float* input_query = (const float*)d_in[0];
    const float* input_key   = (const float*)d_in[1];
    const float* input_value = (const float*)d_in[2];
    const float* loc_vector  = (const float*)d_in[3];
    const float* Wq   = (const float*)d_in[4];
    const float* bq   = (const float*)d_in[5];
    const float* Wk   = (const float*)d_in[6];
    const float* bk   = (const float*)d_in[7];
    const float* Wv   = (const float*)d_in[8];
    const float* bv   = (const float*)d_in[9];
    const float* Wloc = (const float*)d_in[10];
    const float* bloc = (const float*)d_in[11];
    const float* Wlk  = (const float*)d_in[12];
    const float* blk  = (const float*)d_in[13];
    const float* param = (const float*)d_in[14];
    float* out = (float*)d_out;

    float *q1, *q2, *lk, *kloc, *lv;
    cudaGetSymbolAddress((void**)&q1,   g_q1);
    cudaGetSymbolAddress((void**)&q2,   g_q2);
    cudaGetSymbolAddress((void**)&lk,   g_lk);
    cudaGetSymbolAddress((void**)&kloc, g_kloc);
    cudaGetSymbolAddress((void**)&lv,   g_lv);

    dim3 gproj(HDIM / 128, MTOT / 128);      // (16, 25)
    gemm_proj<<<gproj, 256>>>(input_query, Wq,   bq,   q1);
    gemm_proj<<<gproj, 256>>>(loc_vector,  Wloc, bloc, q2);
    gemm_proj<<<gproj, 256>>>(input_key,   Wk,   bk,   lk);
    gemm_proj<<<gproj, 256>>>(loc_vector,  Wlk,  blk,  kloc);
    gemm_proj<<<gproj, 256>>>(input_value, Wv,   bv,   lv);

    size_t tot = (size_t)BATCH * NSEQ * HDIM;
    add_kernel<<<(unsigned)((tot + 255) / 256), 256>>>(param);

    dim3 gsc((NSEQ + 63) / 64, (NSEQ + 63) / 64, BATCH);   // (4,4,16)
    scores_kernel<<<gsc, 256>>>();

    softmax_kernel<<<BATCH * NSEQ, 256>>>();

    dim3 gout(HDIM / 64, (NSEQ + 63) / 64, BATCH);         // (32,4,16)
    out_kernel<<<gout, 256>>>(out);
}

// round 3
// speedup vs baseline: 2.0418x; 2.0418x over previous
#include <cuda_runtime.h>
#include <cuda_bf16.h>
#include <math.h>
#include <stdint.h>

#define BATCH 16
#define NSEQ  200
#define DDIM  2048
#define HDIM  2048
#define MTOT  (BATCH*NSEQ)          // 3200
#define MK    (MTOT*DDIM)
#define KN    (DDIM*HDIM)

// ---------------- scratch (device globals: allocation-guard safe) ----------
__device__ float g_q1[BATCH*NSEQ*HDIM];
__device__ float g_q2[BATCH*NSEQ*HDIM];
__device__ float g_lk[BATCH*NSEQ*HDIM];
__device__ float g_kloc[BATCH*NSEQ*HDIM];
__device__ float g_lv[BATCH*NSEQ*HDIM];
__device__ float g_scores[BATCH*NSEQ*NSEQ];

// bf16 hi/lo split operands.  A mats: 0=query,1=key,2=value,3=loc
__device__ __align__(16) __nv_bfloat16 gA_hi[4*MK];
__device__ __align__(16) __nv_bfloat16 gA_lo[4*MK];
// W mats transposed to [N,K]: 0=Wq,1=Wloc,2=Wk,3=Wlk,4=Wv
__device__ __align__(16) __nv_bfloat16 gW_hi[5*KN];
__device__ __align__(16) __nv_bfloat16 gW_lo[5*KN];

// ============================ helpers ======================================
__device__ __forceinline__ uint32_t smem_u32(const void* p) {
    uint32_t a;
    asm("{ .reg .u64 t; cvta.to.shared.u64 t, %1; cvt.u32.u64 %0, t; }"
        : "=r"(a) : "l"(p));
    return a;
}
__device__ __forceinline__ void cp16(uint32_t dst, const void* src) {
    asm volatile("cp.async.cg.shared.global [%0], [%1], 16;" :: "r"(dst), "l"(src));
}
#define CP_COMMIT() asm volatile("cp.async.commit_group;" ::: "memory")
#define CP_WAIT1()  asm volatile("cp.async.wait_group 1;" ::: "memory")
#define CP_WAIT0()  asm volatile("cp.async.wait_group 0;" ::: "memory")

__device__ __forceinline__ void ldx4(uint32_t addr, uint32_t& r0, uint32_t& r1,
                                     uint32_t& r2, uint32_t& r3) {
    asm volatile("ldmatrix.sync.aligned.m8n8.x4.shared.b16 {%0,%1,%2,%3}, [%4];"
                 : "=r"(r0), "=r"(r1), "=r"(r2), "=r"(r3) : "r"(addr));
}
__device__ __forceinline__ void mma16816(float* c, const uint32_t* a,
                                         const uint32_t* b) {
    asm volatile(
        "mma.sync.aligned.m16n8k16.row.col.f32.bf16.bf16.f32 "
        "{%0,%1,%2,%3}, {%4,%5,%6,%7}, {%8,%9}, {%0,%1,%2,%3};"
        : "+f"(c[0]), "+f"(c[1]), "+f"(c[2]), "+f"(c[3])
        : "r"(a[0]), "r"(a[1]), "r"(a[2]), "r"(a[3]), "r"(b[0]), "r"(b[1]));
}

// =================== conversion kernels ====================================
__global__ __launch_bounds__(256) void convA_kernel(const float* __restrict__ A,
                                                    __nv_bfloat16* __restrict__ hi,
                                                    __nv_bfloat16* __restrict__ lo)
{
    size_t i = ((size_t)blockIdx.x * 256 + threadIdx.x) * 4;
    float4 a = *(const float4*)(A + i);
    __nv_bfloat16 h0 = __float2bfloat16_rn(a.x);
    __nv_bfloat16 h1 = __float2bfloat16_rn(a.y);
    __nv_bfloat16 h2 = __float2bfloat16_rn(a.z);
    __nv_bfloat16 h3 = __float2bfloat16_rn(a.w);
    __nv_bfloat16 l0 = __float2bfloat16_rn(a.x - __bfloat162float(h0));
    __nv_bfloat16 l1 = __float2bfloat16_rn(a.y - __bfloat162float(h1));
    __nv_bfloat16 l2 = __float2bfloat16_rn(a.z - __bfloat162float(h2));
    __nv_bfloat16 l3 = __float2bfloat16_rn(a.w - __bfloat162float(h3));
    ((__nv_bfloat162*)(hi + i))[0] = __nv_bfloat162(h0, h1);
    ((__nv_bfloat162*)(hi + i))[1] = __nv_bfloat162(h2, h3);
    ((__nv_bfloat162*)(lo + i))[0] = __nv_bfloat162(l0, l1);
    ((__nv_bfloat162*)(lo + i))[1] = __nv_bfloat162(l2, l3);
}

// transpose W[K,N] -> Wt[N,K] and split hi/lo
__global__ __launch_bounds__(256) void convW_kernel(const float* __restrict__ W,
                                                    __nv_bfloat16* __restrict__ hi,
                                                    __nv_bfloat16* __restrict__ lo)
{
    __shared__ float t[32][33];
    const int n0 = blockIdx.x * 32, k0 = blockIdx.y * 32;
    const int tx = threadIdx.x, ty = threadIdx.y;
#pragma unroll
    for (int r = ty; r < 32; r += 8)
        t[r][tx] = W[(size_t)(k0 + r) * HDIM + n0 + tx];
    __syncthreads();
#pragma unroll
    for (int r = ty; r < 32; r += 8) {
        float a = t[tx][r];
        __nv_bfloat16 h = __float2bfloat16_rn(a);
        __nv_bfloat16 l = __float2bfloat16_rn(a - __bfloat162float(h));
        size_t off = (size_t)(n0 + r) * DDIM + k0 + tx;
        hi[off] = h;
        lo[off] = l;
    }
}

// =================== HMMA projection GEMM ==================================
// C[3200,2048] = A @ Wt^T + bias.  Tile BM=256 x BN=128, BK=32.
// 512 threads = 16 warps (4 m x 4 n), warp tile 64x32.
// 3-term bf16 split: Ah*Bh + Ah*Bl + Al*Bh.
struct ProjParams {
    const __nv_bfloat16 *Ahi[5], *Alo[5], *Bhi[5], *Blo[5];
    const float* bias[5];
    float* C[5];
};

// per-stage smem layout (pitch 40 bf16 = 80 B per 32-col row):
//   Ahi [256][40] @ 0       (20480 B)
//   Alo [256][40] @ 20480
//   Bhi [128][40] @ 40960   (10240 B)
//   Blo [128][40] @ 51200
#define PSTAGE   61440
#define PSMEM    (2*PSTAGE)      // 122880
#define NCHUNK   64              // 2048/32

__global__ __launch_bounds__(512, 1) void proj_mma(ProjParams P)
{
    extern __shared__ __align__(128) char smem[];
    const int g  = blockIdx.z;
    const int bn = blockIdx.x * 128;
    const int bm = blockIdx.y * 256;
    const int tid  = threadIdx.x;
    const int lane = tid & 31;
    const int wid  = tid >> 5;
    const int wm = (wid & 3) * 64;     // warp m-offset in tile
    const int wn = (wid >> 2) * 32;    // warp n-offset in tile
    const uint32_t sbase = smem_u32(smem);

    const __nv_bfloat16* Ahi = P.Ahi[g];
    const __nv_bfloat16* Alo = P.Alo[g];
    const __nv_bfloat16* Bhi = P.Bhi[g];
    const __nv_bfloat16* Blo = P.Blo[g];
    const float* bias = P.bias[g];
    float* C = P.C[g];

    float acc[4][4][4];
#pragma unroll
    for (int i = 0; i < 4; i++)
#pragma unroll
        for (int j = 0; j < 4; j++)
#pragma unroll
            for (int k = 0; k < 4; k++) acc[i][j][k] = 0.f;

    // ---- async load of one K-chunk into stage s (6 cp16 per thread) ------
    auto load_chunk = [&](int chunk, int s) {
        const int k0 = chunk * 32;
        const uint32_t sb = sbase + s * PSTAGE;
#pragma unroll
        for (int u = 0; u < 6; u++) {
            int idx = u * 512 + tid;
            if (idx < 2048) {                          // A: 2 splits x 256r x 4c
                int split = idx >> 10;
                int i2 = idx & 1023;
                int r = i2 >> 2, c = i2 & 3;
                int row = bm + r; if (row > MTOT - 1) row = MTOT - 1;
                const __nv_bfloat16* src =
                    (split ? Alo : Ahi) + (size_t)row * DDIM + k0 + c * 8;
                cp16(sb + split * 20480 + r * 80 + c * 16, src);
            } else {                                   // B: 2 splits x 128r x 4c
                int j = idx - 2048;
                int split = j >> 9;
                int i2 = j & 511;
                int r = i2 >> 2, c = i2 & 3;
                const __nv_bfloat16* src =
                    (split ? Blo : Bhi) + (size_t)(bn + r) * DDIM + k0 + c * 8;
                cp16(sb + 40960 + split * 10240 + r * 80 + c * 16, src);
            }
        }
    };

    load_chunk(0, 0);
    CP_COMMIT();

    // ldmatrix row/col pattern (same for A and B regions)
    const int lrow = (lane & 7) + ((lane >> 3) & 1) * 8;   // row within 16-block
    const int lcol = (lane >> 4) * 8;                      // k-half select

    for (int it = 0; it < NCHUNK; it++) {
        const int cur = it & 1;
        if (it + 1 < NCHUNK) {
            load_chunk(it + 1, (it + 1) & 1);
            CP_COMMIT();
            CP_WAIT1();
        } else {
            CP_WAIT0();
        }
        __syncthreads();

        const uint32_t sb = sbase + cur * PSTAGE;
#pragma unroll
        for (int ks = 0; ks < 2; ks++) {
            const int colb = (ks * 16 + lcol) * 2;     // byte offset in row
            // B fragments: tiles nj 0..3 (n8 each), hi & lo
            uint32_t Bh[4][2], Bl[4][2];
#pragma unroll
            for (int half = 0; half < 2; half++) {
                const int nrow = wn + half * 16 + lrow;
                uint32_t r0, r1, r2, r3;
                ldx4(sb + 40960 + nrow * 80 + colb, r0, r1, r2, r3);
                Bh[half * 2 + 0][0] = r0; Bh[half * 2 + 1][0] = r1;
                Bh[half * 2 + 0][1] = r2; Bh[half * 2 + 1][1] = r3;
                ldx4(sb + 51200 + nrow * 80 + colb, r0, r1, r2, r3);
                Bl[half * 2 + 0][0] = r0; Bl[half * 2 + 1][0] = r1;
                Bl[half * 2 + 0][1] = r2; Bl[half * 2 + 1][1] = r3;
            }
#pragma unroll
            for (int mi = 0; mi < 4; mi++) {
                const int mrow = wm + mi * 16 + lrow;
                uint32_t ah[4], al[4];
                ldx4(sb + mrow * 80 + colb, ah[0], ah[1], ah[2], ah[3]);
                ldx4(sb + 20480 + mrow * 80 + colb, al[0], al[1], al[2], al[3]);
#pragma unroll
                for (int nj = 0; nj < 4; nj++) {
                    mma16816(acc[mi][nj], ah, Bh[nj]);
                    mma16816(acc[mi][nj], ah, Bl[nj]);
                    mma16816(acc[mi][nj], al, Bh[nj]);
                }
            }
        }
        __syncthreads();
    }

    // ---- epilogue: registers -> gmem with bias ---------------------------
    const int gq = lane >> 2;          // groupID 0..7
    const int tq = lane & 3;           // threadID in group
#pragma unroll
    for (int mi = 0; mi < 4; mi++) {
#pragma unroll
        for (int nj = 0; nj < 4; nj++) {
            int col = bn + wn + nj * 8 + tq * 2;
            float b0 = __ldg(bias + col);
            float b1 = __ldg(bias + col + 1);
            int row0 = bm + wm + mi * 16 + gq;
            if (row0 < MTOT) {
                float2 v = make_float2(acc[mi][nj][0] + b0, acc[mi][nj][1] + b1);
                *(float2*)(C + (size_t)row0 * HDIM + col) = v;
            }
            int row1 = row0 + 8;
            if (row1 < MTOT) {
                float2 v = make_float2(acc[mi][nj][2] + b0, acc[mi][nj][3] + b1);
                *(float2*)(C + (size_t)row1 * HDIM + col) = v;
            }
        }
    }
}

// ---------------- elementwise: q1 = lq + param ; q2 = lq + lloc ------------
__global__ void add_kernel(const float* __restrict__ param)
{
    size_t i = (size_t)blockIdx.x * 256 + threadIdx.x;
    if (i < (size_t)BATCH * NSEQ * HDIM) {
        float lq = g_q1[i];
        float ll = g_q2[i];
        g_q1[i] = lq + param[i];
        g_q2[i] = lq + ll;
    }
}

// ---------------- scores: s[b,n,m] = q1.lk + q2.kloc ----------------------
__global__ __launch_bounds__(256) void scores_kernel()
{
    __shared__ float Qa[16][64], Qb[16][64], Ka[16][64], Kb[16][64];
    const int b  = blockIdx.z;
    const int n0 = blockIdx.y * 64;
    const int m0 = blockIdx.x * 64;
    const size_t bo = (size_t)b * NSEQ * HDIM;
    const float* q1 = g_q1 + bo;
    const float* q2 = g_q2 + bo;
    const float* lk = g_lk + bo;
    const float* kl = g_kloc + bo;

    const int tid = threadIdx.x;
    const int row = tid >> 2;
    const int c4  = (tid & 3) << 2;
    const int ty = tid >> 4, tx = tid & 15;

    float acc[4][4];
#pragma unroll
    for (int i = 0; i < 4; i++)
#pragma unroll
        for (int j = 0; j < 4; j++) acc[i][j] = 0.f;

    for (int k0 = 0; k0 < HDIM; k0 += 16) {
        float4 v;
        if (n0 + row < NSEQ) v = *(const float4*)(q1 + (size_t)(n0 + row) * HDIM + k0 + c4);
        else                 v = make_float4(0, 0, 0, 0);
        Qa[c4 + 0][row] = v.x; Qa[c4 + 1][row] = v.y; Qa[c4 + 2][row] = v.z; Qa[c4 + 3][row] = v.w;
        if (n0 + row < NSEQ) v = *(const float4*)(q2 + (size_t)(n0 + row) * HDIM + k0 + c4);
        else                 v = make_float4(0, 0, 0, 0);
        Qb[c4 + 0][row] = v.x; Qb[c4 + 1][row] = v.y; Qb[c4 + 2][row] = v.z; Qb[c4 + 3][row] = v.w;
        if (m0 + row < NSEQ) v = *(const float4*)(lk + (size_t)(m0 + row) * HDIM + k0 + c4);
        else                 v = make_float4(0, 0, 0, 0);
        Ka[c4 + 0][row] = v.x; Ka[c4 + 1][row] = v.y; Ka[c4 + 2][row] = v.z; Ka[c4 + 3][row] = v.w;
        if (m0 + row < NSEQ) v = *(const float4*)(kl + (size_t)(m0 + row) * HDIM + k0 + c4);
        else                 v = make_float4(0, 0, 0, 0);
        Kb[c4 + 0][row] = v.x; Kb[c4 + 1][row] = v.y; Kb[c4 + 2][row] = v.z; Kb[c4 + 3][row] = v.w;
        __syncthreads();

#pragma unroll
        for (int kk = 0; kk < 16; kk++) {
            float a1[4], a2[4], b1[4], b2[4];
#pragma unroll
            for (int i = 0; i < 4; i++) { a1[i] = Qa[kk][ty * 4 + i]; a2[i] = Qb[kk][ty * 4 + i]; }
#pragma unroll
            for (int j = 0; j < 4; j++) { b1[j] = Ka[kk][tx * 4 + j]; b2[j] = Kb[kk][tx * 4 + j]; }
#pragma unroll
            for (int i = 0; i < 4; i++)
#pragma unroll
                for (int j = 0; j < 4; j++)
                    acc[i][j] = fmaf(a1[i], b1[j], fmaf(a2[i], b2[j], acc[i][j]));
        }
        __syncthreads();
    }

    float* sc = g_scores + (size_t)b * NSEQ * NSEQ;
#pragma unroll
    for (int i = 0; i < 4; i++) {
        int n = n0 + ty * 4 + i;
        if (n >= NSEQ) continue;
#pragma unroll
        for (int j = 0; j < 4; j++) {
            int m = m0 + tx * 4 + j;
            if (m < NSEQ) sc[(size_t)n * NSEQ + m] = acc[i][j];
        }
    }
}

// ---------------- softmax over m (length 200), scaled by 1/sqrt(H) --------
__global__ __launch_bounds__(256) void softmax_kernel()
{
    const int row = blockIdx.x;
    float* s = g_scores + (size_t)row * NSEQ;
    const int tid = threadIdx.x;
    __shared__ float red[8];

    float v = (tid < NSEQ) ? s[tid] : -3.0e38f;
#pragma unroll
    for (int o = 16; o; o >>= 1) v = fmaxf(v, __shfl_xor_sync(0xffffffffu, v, o));
    if ((tid & 31) == 0) red[tid >> 5] = v;
    __syncthreads();
    float vmax = red[0];
#pragma unroll
    for (int w = 1; w < 8; w++) vmax = fmaxf(vmax, red[w]);

    const float scale = 0.02209708691207961f;  // 1/sqrt(2048)
    float e = (tid < NSEQ) ? __expf((s[tid] - vmax) * scale) : 0.f;
    float sum = e;
#pragma unroll
    for (int o = 16; o; o >>= 1) sum += __shfl_xor_sync(0xffffffffu, sum, o);
    __syncthreads();
    if ((tid & 31) == 0) red[tid >> 5] = sum;
    __syncthreads();
    float tot = 0.f;
#pragma unroll
    for (int w = 0; w < 8; w++) tot += red[w];

    if (tid < NSEQ) s[tid] = e / tot;
}

// ---------------- output: out[b,n,o] = sum_m attn[b,n,m] * lv[b,m,o] ------
__global__ __launch_bounds__(256) void out_kernel(float* __restrict__ out)
{
    __shared__ float Ps[16][64];
    __shared__ float Vs[16][64];
    const int b  = blockIdx.z;
    const int n0 = blockIdx.y * 64;
    const int o0 = blockIdx.x * 64;
    const float* attn = g_scores + (size_t)b * NSEQ * NSEQ;
    const float* lv   = g_lv     + (size_t)b * NSEQ * HDIM;

    const int tid = threadIdx.x;
    const int ty = tid >> 4, tx = tid & 15;

    float acc[4][4];
#pragma unroll
    for (int i = 0; i < 4; i++)
#pragma unroll
        for (int j = 0; j < 4; j++) acc[i][j] = 0.f;

    for (int m0 = 0; m0 < NSEQ; m0 += 16) {
        {
            int row = tid >> 2;
            int c4  = (tid & 3) << 2;
            float4 v = make_float4(0, 0, 0, 0);
            int n = n0 + row;
            if (n < NSEQ) {
                int m = m0 + c4;
                if (m + 3 < NSEQ) {
                    v = *(const float4*)(attn + (size_t)n * NSEQ + m);
                } else {
                    const float* p = attn + (size_t)n * NSEQ;
                    v.x = (m + 0 < NSEQ) ? p[m + 0] : 0.f;
                    v.y = (m + 1 < NSEQ) ? p[m + 1] : 0.f;
                    v.z = (m + 2 < NSEQ) ? p[m + 2] : 0.f;
                    v.w = (m + 3 < NSEQ) ? p[m + 3] : 0.f;
                }
            }
            Ps[c4 + 0][row] = v.x; Ps[c4 + 1][row] = v.y;
            Ps[c4 + 2][row] = v.z; Ps[c4 + 3][row] = v.w;
        }
        {
            int row = tid >> 4;
            int c4  = (tid & 15) << 2;
            float4 v = make_float4(0, 0, 0, 0);
            int m = m0 + row;
            if (m < NSEQ)
                v = *(const float4*)(lv + (size_t)m * HDIM + o0 + c4);
            *(float4*)(&Vs[row][c4]) = v;
        }
        __syncthreads();

#pragma unroll
        for (int kk = 0; kk < 16; kk++) {
            float a[4], bfr[4];
#pragma unroll
            for (int i = 0; i < 4; i++) a[i] = Ps[kk][ty * 4 + i];
#pragma unroll
            for (int j = 0; j < 4; j++) bfr[j] = Vs[kk][tx * 4 + j];
#pragma unroll
            for (int i = 0; i < 4; i++)
#pragma unroll
                for (int j = 0; j < 4; j++)
                    acc[i][j] = fmaf(a[i], bfr[j], acc[i][j]);
        }
        __syncthreads();
    }

#pragma unroll
    for (int i = 0; i < 4; i++) {
        int n = n0 + ty * 4 + i;
        if (n >= NSEQ) continue;
        size_t off = ((size_t)b * NSEQ + n) * HDIM + o0 + tx * 4;
        float4 v = make_float4(acc[i][0], acc[i][1], acc[i][2], acc[i][3]);
        *(float4*)(out + off) = v;
    }
}

// ---------------------------------------------------------------------------
extern "C" void kernel_launch(void* const* d_in, const int* in_sizes, int n_in,
                              void* d_out, int out_size)
{
    const float* input_query = (const float*)d_in[0];
    const float* input_key   = (const float*)d_in[1];
    const float* input_value = (const float*)d_in[2];
    const float* loc_vector  = (const float*)d_in[3];
    const float* Wq   = (const float*)d_in[4];
    const float* bq   = (const float*)d_in[5];
    const float* Wk   = (const float*)d_in[6];
    const float* bk   = (const float*)d_in[7];
    const float* Wv   = (const float*)d_in[8];
    const float* bv   = (const float*)d_in[9];
    const float* Wloc = (const float*)d_in[10];
    const float* bloc = (const float*)d_in[11];
    const float* Wlk  = (const float*)d_in[12];
    const float* blk  = (const float*)d_in[13];
    const float* param = (const float*)d_in[14];
    float* out = (float*)d_out;

    float *q1, *q2, *lk, *kloc, *lv;
    cudaGetSymbolAddress((void**)&q1,   g_q1);
    cudaGetSymbolAddress((void**)&q2,   g_q2);
    cudaGetSymbolAddress((void**)&lk,   g_lk);
    cudaGetSymbolAddress((void**)&kloc, g_kloc);
    cudaGetSymbolAddress((void**)&lv,   g_lv);

    __nv_bfloat16 *Ahi, *Alo, *Whi, *Wlo;
    cudaGetSymbolAddress((void**)&Ahi, gA_hi);
    cudaGetSymbolAddress((void**)&Alo, gA_lo);
    cudaGetSymbolAddress((void**)&Whi, gW_hi);
    cudaGetSymbolAddress((void**)&Wlo, gW_lo);

    cudaFuncSetAttribute(proj_mma, cudaFuncAttributeMaxDynamicSharedMemorySize,
                         PSMEM);

    // conversions: A mats 0=query,1=key,2=value,3=loc
    const float* Amats[4] = {input_query, input_key, input_value, loc_vector};
    for (int m = 0; m < 4; m++)
        convA_kernel<<<MK / 1024, 256>>>(Amats[m], Ahi + (size_t)m * MK,
                                         Alo + (size_t)m * MK);
    // W mats (gemm order): 0=Wq,1=Wloc,2=Wk,3=Wlk,4=Wv
    const float* Wmats[5] = {Wq, Wloc, Wk, Wlk, Wv};
    for (int w = 0; w < 5; w++)
        convW_kernel<<<dim3(HDIM / 32, DDIM / 32), dim3(32, 8)>>>(
            Wmats[w], Whi + (size_t)w * KN, Wlo + (size_t)w * KN);

    // fused 5-GEMM projection launch
    ProjParams P;
    const int aidx[5] = {0, 3, 1, 3, 2};       // query, loc, key, loc, value
    const float* biases[5] = {bq, bloc, bk, blk, bv};
    float* outs[5] = {q1, q2, lk, kloc, lv};
    for (int g = 0; g < 5; g++) {
        P.Ahi[g]  = Ahi + (size_t)aidx[g] * MK;
        P.Alo[g]  = Alo + (size_t)aidx[g] * MK;
        P.Bhi[g]  = Whi + (size_t)g * KN;
        P.Blo[g]  = Wlo + (size_t)g * KN;
        P.bias[g] = biases[g];
        P.C[g]    = outs[g];
    }
    proj_mma<<<dim3(HDIM / 128, (MTOT + 255) / 256, 5), 512, PSMEM>>>(P);

    size_t tot = (size_t)BATCH * NSEQ * HDIM;
    add_kernel<<<(unsigned)((tot + 255) / 256), 256>>>(param);

    dim3 gsc((NSEQ + 63) / 64, (NSEQ + 63) / 64, BATCH);
    scores_kernel<<<gsc, 256>>>();

    softmax_kernel<<<BATCH * NSEQ, 256>>>();

    dim3 gout(HDIM / 64, (NSEQ + 63) / 64, BATCH);
    out_kernel<<<gout, 256>>>(out);
}

// round 4
// speedup vs baseline: 2.2097x; 1.0822x over previous
#include <cuda_runtime.h>
#include <cuda_bf16.h>
#include <math.h>
#include <stdint.h>

#define BATCH 16
#define NSEQ  200
#define DDIM  2048
#define HDIM  2048
#define MTOT  (BATCH*NSEQ)          // 3200
#define MK    (MTOT*DDIM)
#define KN    (DDIM*HDIM)
#define KCAT  4096                  // scores concatenated K
#define KOUT  224                   // out GEMM K (200 padded to 32-mult)

// ---------------- scratch (device globals) ---------------------------------
__device__ float g_q1[BATCH*NSEQ*HDIM];      // lq
__device__ float g_q2[BATCH*NSEQ*HDIM];      // lloc
__device__ float g_lk[BATCH*NSEQ*HDIM];
__device__ float g_kloc[BATCH*NSEQ*HDIM];
__device__ float g_lv[BATCH*NSEQ*HDIM];
__device__ float g_scores[BATCH*NSEQ*NSEQ];

// bf16 hi/lo split operands for projections
__device__ __align__(16) __nv_bfloat16 gA_hi[4*MK];
__device__ __align__(16) __nv_bfloat16 gA_lo[4*MK];
__device__ __align__(16) __nv_bfloat16 gW_hi[5*KN];
__device__ __align__(16) __nv_bfloat16 gW_lo[5*KN];

// score-GEMM operands: [b][n][4096] = [q1 | q2], [lk | kloc]
__device__ __align__(16) __nv_bfloat16 gQc_hi[BATCH*NSEQ*KCAT];
__device__ __align__(16) __nv_bfloat16 gQc_lo[BATCH*NSEQ*KCAT];
__device__ __align__(16) __nv_bfloat16 gKc_hi[BATCH*NSEQ*KCAT];
__device__ __align__(16) __nv_bfloat16 gKc_lo[BATCH*NSEQ*KCAT];

// out-GEMM operands
__device__ __align__(16) __nv_bfloat16 gAttn_hi[BATCH*NSEQ*KOUT];
__device__ __align__(16) __nv_bfloat16 gAttn_lo[BATCH*NSEQ*KOUT];
__device__ __align__(16) __nv_bfloat16 gLvT_hi[BATCH*HDIM*KOUT];
__device__ __align__(16) __nv_bfloat16 gLvT_lo[BATCH*HDIM*KOUT];

// ============================ helpers ======================================
__device__ __forceinline__ uint32_t smem_u32(const void* p) {
    uint32_t a;
    asm("{ .reg .u64 t; cvta.to.shared.u64 t, %1; cvt.u32.u64 %0, t; }"
        : "=r"(a) : "l"(p));
    return a;
}
__device__ __forceinline__ void cp16(uint32_t dst, const void* src) {
    asm volatile("cp.async.cg.shared.global [%0], [%1], 16;" :: "r"(dst), "l"(src));
}
#define CP_COMMIT() asm volatile("cp.async.commit_group;" ::: "memory")
#define CP_WAIT1()  asm volatile("cp.async.wait_group 1;" ::: "memory")
#define CP_WAIT0()  asm volatile("cp.async.wait_group 0;" ::: "memory")

__device__ __forceinline__ void ldx4(uint32_t addr, uint32_t& r0, uint32_t& r1,
                                     uint32_t& r2, uint32_t& r3) {
    asm volatile("ldmatrix.sync.aligned.m8n8.x4.shared.b16 {%0,%1,%2,%3}, [%4];"
                 : "=r"(r0), "=r"(r1), "=r"(r2), "=r"(r3) : "r"(addr));
}
__device__ __forceinline__ void mma16816(float* c, const uint32_t* a,
                                         const uint32_t* b) {
    asm volatile(
        "mma.sync.aligned.m16n8k16.row.col.f32.bf16.bf16.f32 "
        "{%0,%1,%2,%3}, {%4,%5,%6,%7}, {%8,%9}, {%0,%1,%2,%3};"
        : "+f"(c[0]), "+f"(c[1]), "+f"(c[2]), "+f"(c[3])
        : "r"(a[0]), "r"(a[1]), "r"(a[2]), "r"(a[3]), "r"(b[0]), "r"(b[1]));
}
__device__ __forceinline__ void split_bf16(float x, __nv_bfloat16& h,
                                           __nv_bfloat16& l) {
    h = __float2bfloat16_rn(x);
    l = __float2bfloat16_rn(x - __bfloat162float(h));
}

// =================== conversion kernels ====================================
__global__ __launch_bounds__(256) void convA_kernel(const float* __restrict__ A,
                                                    __nv_bfloat16* __restrict__ hi,
                                                    __nv_bfloat16* __restrict__ lo)
{
    size_t i = ((size_t)blockIdx.x * 256 + threadIdx.x) * 4;
    float4 a = *(const float4*)(A + i);
    __nv_bfloat16 h0, h1, h2, h3, l0, l1, l2, l3;
    split_bf16(a.x, h0, l0); split_bf16(a.y, h1, l1);
    split_bf16(a.z, h2, l2); split_bf16(a.w, h3, l3);
    ((__nv_bfloat162*)(hi + i))[0] = __nv_bfloat162(h0, h1);
    ((__nv_bfloat162*)(hi + i))[1] = __nv_bfloat162(h2, h3);
    ((__nv_bfloat162*)(lo + i))[0] = __nv_bfloat162(l0, l1);
    ((__nv_bfloat162*)(lo + i))[1] = __nv_bfloat162(l2, l3);
}

// transpose W[K,N] -> Wt[N,K], split hi/lo
__global__ __launch_bounds__(256) void convW_kernel(const float* __restrict__ W,
                                                    __nv_bfloat16* __restrict__ hi,
                                                    __nv_bfloat16* __restrict__ lo)
{
    __shared__ float t[32][33];
    const int n0 = blockIdx.x * 32, k0 = blockIdx.y * 32;
    const int tx = threadIdx.x, ty = threadIdx.y;
#pragma unroll
    for (int r = ty; r < 32; r += 8)
        t[r][tx] = W[(size_t)(k0 + r) * HDIM + n0 + tx];
    __syncthreads();
#pragma unroll
    for (int r = ty; r < 32; r += 8) {
        __nv_bfloat16 h, l;
        split_bf16(t[tx][r], h, l);
        size_t off = (size_t)(n0 + r) * DDIM + k0 + tx;
        hi[off] = h;
        lo[off] = l;
    }
}

// =================== HMMA projection GEMM ==================================
// C[3200,2048] = A @ Wt^T + bias.  BM=256 x BN=128, BK=32, 512 thr (4x4 warps).
struct ProjParams {
    const __nv_bfloat16 *Ahi[5], *Alo[5], *Bhi[5], *Blo[5];
    const float* bias[5];
    float* C[5];
};

#define PSTAGE   61440   // Ahi 20480 | Alo 20480 | Bhi 10240 | Blo 10240
#define PSMEM    (2*PSTAGE)
#define NCHUNK   64

__global__ __launch_bounds__(512, 1) void proj_mma(ProjParams P)
{
    extern __shared__ __align__(128) char smem[];
    const int g  = blockIdx.z;
    const int bn = blockIdx.x * 128;
    const int bm = blockIdx.y * 256;
    const int tid  = threadIdx.x;
    const int lane = tid & 31;
    const int wid  = tid >> 5;
    const int wm = (wid & 3) * 64;
    const int wn = (wid >> 2) * 32;
    const uint32_t sbase = smem_u32(smem);

    const __nv_bfloat16* Ahi = P.Ahi[g];
    const __nv_bfloat16* Alo = P.Alo[g];
    const __nv_bfloat16* Bhi = P.Bhi[g];
    const __nv_bfloat16* Blo = P.Blo[g];
    const float* bias = P.bias[g];
    float* C = P.C[g];

    float acc[4][4][4];
#pragma unroll
    for (int i = 0; i < 4; i++)
#pragma unroll
        for (int j = 0; j < 4; j++)
#pragma unroll
            for (int k = 0; k < 4; k++) acc[i][j][k] = 0.f;

    auto load_chunk = [&](int chunk, int s) {
        const int k0 = chunk * 32;
        const uint32_t sb = sbase + s * PSTAGE;
#pragma unroll
        for (int u = 0; u < 6; u++) {
            int idx = u * 512 + tid;
            if (idx < 2048) {
                int split = idx >> 10;
                int i2 = idx & 1023;
                int r = i2 >> 2, c = i2 & 3;
                int row = bm + r; if (row > MTOT - 1) row = MTOT - 1;
                const __nv_bfloat16* src =
                    (split ? Alo : Ahi) + (size_t)row * DDIM + k0 + c * 8;
                cp16(sb + split * 20480 + r * 80 + c * 16, src);
            } else {
                int j = idx - 2048;
                int split = j >> 9;
                int i2 = j & 511;
                int r = i2 >> 2, c = i2 & 3;
                const __nv_bfloat16* src =
                    (split ? Blo : Bhi) + (size_t)(bn + r) * DDIM + k0 + c * 8;
                cp16(sb + 40960 + split * 10240 + r * 80 + c * 16, src);
            }
        }
    };

    load_chunk(0, 0);
    CP_COMMIT();

    const int lrow = (lane & 7) + ((lane >> 3) & 1) * 8;
    const int lcol = (lane >> 4) * 8;

    for (int it = 0; it < NCHUNK; it++) {
        const int cur = it & 1;
        if (it + 1 < NCHUNK) {
            load_chunk(it + 1, (it + 1) & 1);
            CP_COMMIT();
            CP_WAIT1();
        } else {
            CP_WAIT0();
        }
        __syncthreads();

        const uint32_t sb = sbase + cur * PSTAGE;
#pragma unroll
        for (int ks = 0; ks < 2; ks++) {
            const int colb = (ks * 16 + lcol) * 2;
            uint32_t Bh[4][2], Bl[4][2];
#pragma unroll
            for (int half = 0; half < 2; half++) {
                const int nrow = wn + half * 16 + lrow;
                uint32_t r0, r1, r2, r3;
                ldx4(sb + 40960 + nrow * 80 + colb, r0, r1, r2, r3);
                Bh[half * 2 + 0][0] = r0; Bh[half * 2 + 1][0] = r1;
                Bh[half * 2 + 0][1] = r2; Bh[half * 2 + 1][1] = r3;
                ldx4(sb + 51200 + nrow * 80 + colb, r0, r1, r2, r3);
                Bl[half * 2 + 0][0] = r0; Bl[half * 2 + 1][0] = r1;
                Bl[half * 2 + 0][1] = r2; Bl[half * 2 + 1][1] = r3;
            }
            // term-major, 2-mi batching: acc chains spaced by 8 MMAs
#pragma unroll
            for (int p = 0; p < 2; p++) {
                uint32_t ah[2][4], al[2][4];
#pragma unroll
                for (int m2 = 0; m2 < 2; m2++) {
                    const int mrow = wm + (p * 2 + m2) * 16 + lrow;
                    ldx4(sb + mrow * 80 + colb,
                         ah[m2][0], ah[m2][1], ah[m2][2], ah[m2][3]);
                    ldx4(sb + 20480 + mrow * 80 + colb,
                         al[m2][0], al[m2][1], al[m2][2], al[m2][3]);
                }
#pragma unroll
                for (int m2 = 0; m2 < 2; m2++)
#pragma unroll
                    for (int nj = 0; nj < 4; nj++)
                        mma16816(acc[p * 2 + m2][nj], ah[m2], Bh[nj]);
#pragma unroll
                for (int m2 = 0; m2 < 2; m2++)
#pragma unroll
                    for (int nj = 0; nj < 4; nj++)
                        mma16816(acc[p * 2 + m2][nj], ah[m2], Bl[nj]);
#pragma unroll
                for (int m2 = 0; m2 < 2; m2++)
#pragma unroll
                    for (int nj = 0; nj < 4; nj++)
                        mma16816(acc[p * 2 + m2][nj], al[m2], Bh[nj]);
            }
        }
        __syncthreads();
    }

    const int gq = lane >> 2;
    const int tq = lane & 3;
#pragma unroll
    for (int mi = 0; mi < 4; mi++) {
#pragma unroll
        for (int nj = 0; nj < 4; nj++) {
            int col = bn + wn + nj * 8 + tq * 2;
            float b0 = __ldg(bias + col);
            float b1 = __ldg(bias + col + 1);
            int row0 = bm + wm + mi * 16 + gq;
            if (row0 < MTOT) {
                float2 v = make_float2(acc[mi][nj][0] + b0, acc[mi][nj][1] + b1);
                *(float2*)(C + (size_t)row0 * HDIM + col) = v;
            }
            int row1 = row0 + 8;
            if (row1 < MTOT) {
                float2 v = make_float2(acc[mi][nj][2] + b0, acc[mi][nj][3] + b1);
                *(float2*)(C + (size_t)row1 * HDIM + col) = v;
            }
        }
    }
}

// =============== qk pack: build concat bf16 hi/lo operands =================
// qcat = [lq+param | lq+lloc], kcat = [lk | kloc], row length 4096
__global__ __launch_bounds__(256) void qkpack_kernel(const float* __restrict__ param)
{
    size_t i2 = (size_t)blockIdx.x * 256 + threadIdx.x;   // pair index
    if (i2 >= (size_t)BATCH * NSEQ * HDIM / 2) return;
    size_t i = i2 * 2;
    size_t bn = i / HDIM;          // b*200+n
    int    h  = (int)(i % HDIM);
    size_t base = bn * KCAT + h;

    float2 lq = *(const float2*)(g_q1 + i);
    float2 ll = *(const float2*)(g_q2 + i);
    float2 pp = *(const float2*)(param + i);
    float2 lk = *(const float2*)(g_lk + i);
    float2 kl = *(const float2*)(g_kloc + i);

    __nv_bfloat16 h0, l0, h1, l1;
    split_bf16(lq.x + pp.x, h0, l0); split_bf16(lq.y + pp.y, h1, l1);
    *(__nv_bfloat162*)(gQc_hi + base) = __nv_bfloat162(h0, h1);
    *(__nv_bfloat162*)(gQc_lo + base) = __nv_bfloat162(l0, l1);
    split_bf16(lq.x + ll.x, h0, l0); split_bf16(lq.y + ll.y, h1, l1);
    *(__nv_bfloat162*)(gQc_hi + base + DDIM) = __nv_bfloat162(h0, h1);
    *(__nv_bfloat162*)(gQc_lo + base + DDIM) = __nv_bfloat162(l0, l1);
    split_bf16(lk.x, h0, l0); split_bf16(lk.y, h1, l1);
    *(__nv_bfloat162*)(gKc_hi + base) = __nv_bfloat162(h0, h1);
    *(__nv_bfloat162*)(gKc_lo + base) = __nv_bfloat162(l0, l1);
    split_bf16(kl.x, h0, l0); split_bf16(kl.y, h1, l1);
    *(__nv_bfloat162*)(gKc_hi + base + DDIM) = __nv_bfloat162(h0, h1);
    *(__nv_bfloat162*)(gKc_lo + base + DDIM) = __nv_bfloat162(l0, l1);
}

// =================== HMMA scores GEMM ======================================
// scores[b][n][m] = qcat[b][n][:] . kcat[b][m][:], K=4096, 3-term bf16.
// Tile 128x128, BK=32, 256 thr = 8 warps (2m x 4n), warp tile 64x32.
#define SSTAGE 40960   // Ahi 10240 | Alo 10240 | Bhi 10240 | Blo 10240
#define SSMEM  (2*SSTAGE)
#define SNCHUNK 128

__global__ __launch_bounds__(256, 1) void scores_mma()
{
    extern __shared__ __align__(128) char smem[];
    const int b  = blockIdx.z;
    const int m0 = blockIdx.x * 128;
    const int n0 = blockIdx.y * 128;
    const int tid  = threadIdx.x;
    const int lane = tid & 31;
    const int wid  = tid >> 5;
    const int wm = (wid & 1) * 64;
    const int wn = (wid >> 1) * 32;
    const uint32_t sbase = smem_u32(smem);

    const size_t bo = (size_t)b * NSEQ * KCAT;
    const __nv_bfloat16* Ahi = gQc_hi + bo;
    const __nv_bfloat16* Alo = gQc_lo + bo;
    const __nv_bfloat16* Bhi = gKc_hi + bo;
    const __nv_bfloat16* Blo = gKc_lo + bo;

    float acc[4][4][4];
#pragma unroll
    for (int i = 0; i < 4; i++)
#pragma unroll
        for (int j = 0; j < 4; j++)
#pragma unroll
            for (int k = 0; k < 4; k++) acc[i][j][k] = 0.f;

    auto load_chunk = [&](int chunk, int s) {
        const int k0 = chunk * 32;
        const uint32_t sb = sbase + s * SSTAGE;
#pragma unroll
        for (int u = 0; u < 8; u++) {
            int idx = u * 256 + tid;
            int reg = idx >> 10;            // 0:A 1:B
            int j = idx & 1023;
            int split = j >> 9;
            int i2 = j & 511;
            int r = i2 >> 2, c = i2 & 3;
            int row = (reg ? m0 : n0) + r;
            if (row > NSEQ - 1) row = NSEQ - 1;
            const __nv_bfloat16* base =
                reg ? (split ? Blo : Bhi) : (split ? Alo : Ahi);
            cp16(sb + reg * 20480 + split * 10240 + r * 80 + c * 16,
                 base + (size_t)row * KCAT + k0 + c * 8);
        }
    };

    load_chunk(0, 0);
    CP_COMMIT();

    const int lrow = (lane & 7) + ((lane >> 3) & 1) * 8;
    const int lcol = (lane >> 4) * 8;

    for (int it = 0; it < SNCHUNK; it++) {
        const int cur = it & 1;
        if (it + 1 < SNCHUNK) {
            load_chunk(it + 1, (it + 1) & 1);
            CP_COMMIT();
            CP_WAIT1();
        } else {
            CP_WAIT0();
        }
        __syncthreads();

        const uint32_t sb = sbase + cur * SSTAGE;
#pragma unroll
        for (int ks = 0; ks < 2; ks++) {
            const int colb = (ks * 16 + lcol) * 2;
            uint32_t Bh[4][2], Bl[4][2];
#pragma unroll
            for (int half = 0; half < 2; half++) {
                const int nrow = wn + half * 16 + lrow;
                uint32_t r0, r1, r2, r3;
                ldx4(sb + 20480 + nrow * 80 + colb, r0, r1, r2, r3);
                Bh[half * 2 + 0][0] = r0; Bh[half * 2 + 1][0] = r1;
                Bh[half * 2 + 0][1] = r2; Bh[half * 2 + 1][1] = r3;
                ldx4(sb + 30720 + nrow * 80 + colb, r0, r1, r2, r3);
                Bl[half * 2 + 0][0] = r0; Bl[half * 2 + 1][0] = r1;
                Bl[half * 2 + 0][1] = r2; Bl[half * 2 + 1][1] = r3;
            }
#pragma unroll
            for (int p = 0; p < 2; p++) {
                uint32_t ah[2][4], al[2][4];
#pragma unroll
                for (int m2 = 0; m2 < 2; m2++) {
                    const int mrow = wm + (p * 2 + m2) * 16 + lrow;
                    ldx4(sb + mrow * 80 + colb,
                         ah[m2][0], ah[m2][1], ah[m2][2], ah[m2][3]);
                    ldx4(sb + 10240 + mrow * 80 + colb,
                         al[m2][0], al[m2][1], al[m2][2], al[m2][3]);
                }
#pragma unroll
                for (int m2 = 0; m2 < 2; m2++)
#pragma unroll
                    for (int nj = 0; nj < 4; nj++)
                        mma16816(acc[p * 2 + m2][nj], ah[m2], Bh[nj]);
#pragma unroll
                for (int m2 = 0; m2 < 2; m2++)
#pragma unroll
                    for (int nj = 0; nj < 4; nj++)
                        mma16816(acc[p * 2 + m2][nj], ah[m2], Bl[nj]);
#pragma unroll
                for (int m2 = 0; m2 < 2; m2++)
#pragma unroll
                    for (int nj = 0; nj < 4; nj++)
                        mma16816(acc[p * 2 + m2][nj], al[m2], Bh[nj]);
            }
        }
        __syncthreads();
    }

    float* sc = g_scores + (size_t)b * NSEQ * NSEQ;
    const int gq = lane >> 2;
    const int tq = lane & 3;
#pragma unroll
    for (int mi = 0; mi < 4; mi++) {
#pragma unroll
        for (int nj = 0; nj < 4; nj++) {
            int col = m0 + wn + nj * 8 + tq * 2;
            if (col >= NSEQ) continue;
            int row0 = n0 + wm + mi * 16 + gq;
            if (row0 < NSEQ)
                *(float2*)(sc + (size_t)row0 * NSEQ + col) =
                    make_float2(acc[mi][nj][0], acc[mi][nj][1]);
            int row1 = row0 + 8;
            if (row1 < NSEQ)
                *(float2*)(sc + (size_t)row1 * NSEQ + col) =
                    make_float2(acc[mi][nj][2], acc[mi][nj][3]);
        }
    }
}

// ---------------- softmax -> bf16 hi/lo attn (padded to 224) --------------
__global__ __launch_bounds__(256) void softmax_kernel()
{
    const int row = blockIdx.x;                // b*200+n
    float* s = g_scores + (size_t)row * NSEQ;
    const int tid = threadIdx.x;
    __shared__ float red[8];

    float v = (tid < NSEQ) ? s[tid] : -3.0e38f;
#pragma unroll
    for (int o = 16; o; o >>= 1) v = fmaxf(v, __shfl_xor_sync(0xffffffffu, v, o));
    if ((tid & 31) == 0) red[tid >> 5] = v;
    __syncthreads();
    float vmax = red[0];
#pragma unroll
    for (int w = 1; w < 8; w++) vmax = fmaxf(vmax, red[w]);

    const float scale = 0.02209708691207961f;  // 1/sqrt(2048)
    float e = (tid < NSEQ) ? __expf((s[tid] - vmax) * scale) : 0.f;
    float sum = e;
#pragma unroll
    for (int o = 16; o; o >>= 1) sum += __shfl_xor_sync(0xffffffffu, sum, o);
    __syncthreads();
    if ((tid & 31) == 0) red[tid >> 5] = sum;
    __syncthreads();
    float tot = 0.f;
#pragma unroll
    for (int w = 0; w < 8; w++) tot += red[w];

    if (tid < KOUT) {
        float a = (tid < NSEQ) ? e / tot : 0.f;
        __nv_bfloat16 h, l;
        split_bf16(a, h, l);
        gAttn_hi[(size_t)row * KOUT + tid] = h;
        gAttn_lo[(size_t)row * KOUT + tid] = l;
    }
}

// ---------------- lv transpose + split: lvT[b][o][m] ----------------------
__global__ __launch_bounds__(256) void lvT_kernel()
{
    __shared__ float t[32][33];
    const int b  = blockIdx.z;
    const int o0 = blockIdx.x * 32;
    const int m0 = blockIdx.y * 32;
    const int tx = threadIdx.x, ty = threadIdx.y;
    const float* lv = g_lv + (size_t)b * NSEQ * HDIM;
#pragma unroll
    for (int r = ty; r < 32; r += 8) {
        int m = m0 + r;
        t[r][tx] = (m < NSEQ) ? lv[(size_t)m * HDIM + o0 + tx] : 0.f;
    }
    __syncthreads();
#pragma unroll
    for (int r = ty; r < 32; r += 8) {
        __nv_bfloat16 h, l;
        split_bf16(t[tx][r], h, l);
        size_t off = ((size_t)b * HDIM + o0 + r) * KOUT + m0 + tx;
        gLvT_hi[off] = h;
        gLvT_lo[off] = l;
    }
}

// =================== HMMA output GEMM ======================================
// out[b][n][o] = attn[b][n][:K224] . lvT[b][o][:K224], 3-term bf16.
// Tile 128(n) x 128(o), BK=32, 256 thr, same structure as scores_mma.
#define ONCHUNK 7   // 224/32

__global__ __launch_bounds__(256, 1) void out_mma(float* __restrict__ out)
{
    extern __shared__ __align__(128) char smem[];
    const int b  = blockIdx.z;
    const int o0 = blockIdx.x * 128;
    const int n0 = blockIdx.y * 128;
    const int tid  = threadIdx.x;
    const int lane = tid & 31;
    const int wid  = tid >> 5;
    const int wm = (wid & 1) * 64;
    const int wn = (wid >> 1) * 32;
    const uint32_t sbase = smem_u32(smem);

    const __nv_bfloat16* Ahi = gAttn_hi + (size_t)b * NSEQ * KOUT;
    const __nv_bfloat16* Alo = gAttn_lo + (size_t)b * NSEQ * KOUT;
    const __nv_bfloat16* Bhi = gLvT_hi + (size_t)b * HDIM * KOUT;
    const __nv_bfloat16* Blo = gLvT_lo + (size_t)b * HDIM * KOUT;

    float acc[4][4][4];
#pragma unroll
    for (int i = 0; i < 4; i++)
#pragma unroll
        for (int j = 0; j < 4; j++)
#pragma unroll
            for (int k = 0; k < 4; k++) acc[i][j][k] = 0.f;

    auto load_chunk = [&](int chunk, int s) {
        const int k0 = chunk * 32;
        const uint32_t sb = sbase + s * SSTAGE;
#pragma unroll
        for (int u = 0; u < 8; u++) {
            int idx = u * 256 + tid;
            int reg = idx >> 10;
            int j = idx & 1023;
            int split = j >> 9;
            int i2 = j & 511;
            int r = i2 >> 2, c = i2 & 3;
            const __nv_bfloat16* base;
            size_t off;
            if (reg == 0) {                     // attn rows (n)
                int row = n0 + r; if (row > NSEQ - 1) row = NSEQ - 1;
                base = split ? Alo : Ahi;
                off = (size_t)row * KOUT + k0 + c * 8;
            } else {                            // lvT rows (o)
                base = split ? Blo : Bhi;
                off = (size_t)(o0 + r) * KOUT + k0 + c * 8;
            }
            cp16(sb + reg * 20480 + split * 10240 + r * 80 + c * 16, base + off);
        }
    };

    load_chunk(0, 0);
    CP_COMMIT();

    const int lrow = (lane & 7) + ((lane >> 3) & 1) * 8;
    const int lcol = (lane >> 4) * 8;

    for (int it = 0; it < ONCHUNK; it++) {
        const int cur = it & 1;
        if (it + 1 < ONCHUNK) {
            load_chunk(it + 1, (it + 1) & 1);
            CP_COMMIT();
            CP_WAIT1();
        } else {
            CP_WAIT0();
        }
        __syncthreads();

        const uint32_t sb = sbase + cur * SSTAGE;
#pragma unroll
        for (int ks = 0; ks < 2; ks++) {
            const int colb = (ks * 16 + lcol) * 2;
            uint32_t Bh[4][2], Bl[4][2];
#pragma unroll
            for (int half = 0; half < 2; half++) {
                const int nrow = wn + half * 16 + lrow;
                uint32_t r0, r1, r2, r3;
                ldx4(sb + 20480 + nrow * 80 + colb, r0, r1, r2, r3);
                Bh[half * 2 + 0][0] = r0; Bh[half * 2 + 1][0] = r1;
                Bh[half * 2 + 0][1] = r2; Bh[half * 2 + 1][1] = r3;
                ldx4(sb + 30720 + nrow * 80 + colb, r0, r1, r2, r3);
                Bl[half * 2 + 0][0] = r0; Bl[half * 2 + 1][0] = r1;
                Bl[half * 2 + 0][1] = r2; Bl[half * 2 + 1][1] = r3;
            }
#pragma unroll
            for (int p = 0; p < 2; p++) {
                uint32_t ah[2][4], al[2][4];
#pragma unroll
                for (int m2 = 0; m2 < 2; m2++) {
                    const int mrow = wm + (p * 2 + m2) * 16 + lrow;
                    ldx4(sb + mrow * 80 + colb,
                         ah[m2][0], ah[m2][1], ah[m2][2], ah[m2][3]);
                    ldx4(sb + 10240 + mrow * 80 + colb,
                         al[m2][0], al[m2][1], al[m2][2], al[m2][3]);
                }
#pragma unroll
                for (int m2 = 0; m2 < 2; m2++)
#pragma unroll
                    for (int nj = 0; nj < 4; nj++)
                        mma16816(acc[p * 2 + m2][nj], ah[m2], Bh[nj]);
#pragma unroll
                for (int m2 = 0; m2 < 2; m2++)
#pragma unroll
                    for (int nj = 0; nj < 4; nj++)
                        mma16816(acc[p * 2 + m2][nj], ah[m2], Bl[nj]);
#pragma unroll
                for (int m2 = 0; m2 < 2; m2++)
#pragma unroll
                    for (int nj = 0; nj < 4; nj++)
                        mma16816(acc[p * 2 + m2][nj], al[m2], Bh[nj]);
            }
        }
        __syncthreads();
    }

    const int gq = lane >> 2;
    const int tq = lane & 3;
#pragma unroll
    for (int mi = 0; mi < 4; mi++) {
#pragma unroll
        for (int nj = 0; nj < 4; nj++) {
            int col = o0 + wn + nj * 8 + tq * 2;
            int row0 = n0 + wm + mi * 16 + gq;
            if (row0 < NSEQ)
                *(float2*)(out + ((size_t)b * NSEQ + row0) * HDIM + col) =
                    make_float2(acc[mi][nj][0], acc[mi][nj][1]);
            int row1 = row0 + 8;
            if (row1 < NSEQ)
                *(float2*)(out + ((size_t)b * NSEQ + row1) * HDIM + col) =
                    make_float2(acc[mi][nj][2], acc[mi][nj][3]);
        }
    }
}

// ---------------------------------------------------------------------------
extern "C" void kernel_launch(void* const* d_in, const int* in_sizes, int n_in,
                              void* d_out, int out_size)
{
    const float* input_query = (const float*)d_in[0];
    const float* input_key   = (const float*)d_in[1];
    const float* input_value = (const float*)d_in[2];
    const float* loc_vector  = (const float*)d_in[3];
    const float* Wq   = (const float*)d_in[4];
    const float* bq   = (const float*)d_in[5];
    const float* Wk   = (const float*)d_in[6];
    const float* bk   = (const float*)d_in[7];
    const float* Wv   = (const float*)d_in[8];
    const float* bv   = (const float*)d_in[9];
    const float* Wloc = (const float*)d_in[10];
    const float* bloc = (const float*)d_in[11];
    const float* Wlk  = (const float*)d_in[12];
    const float* blk  = (const float*)d_in[13];
    const float* param = (const float*)d_in[14];
    float* out = (float*)d_out;

    float *q1, *q2, *lk, *kloc, *lv;
    cudaGetSymbolAddress((void**)&q1,   g_q1);
    cudaGetSymbolAddress((void**)&q2,   g_q2);
    cudaGetSymbolAddress((void**)&lk,   g_lk);
    cudaGetSymbolAddress((void**)&kloc, g_kloc);
    cudaGetSymbolAddress((void**)&lv,   g_lv);

    __nv_bfloat16 *Ahi, *Alo, *Whi, *Wlo;
    cudaGetSymbolAddress((void**)&Ahi, gA_hi);
    cudaGetSymbolAddress((void**)&Alo, gA_lo);
    cudaGetSymbolAddress((void**)&Whi, gW_hi);
    cudaGetSymbolAddress((void**)&Wlo, gW_lo);

    cudaFuncSetAttribute(proj_mma, cudaFuncAttributeMaxDynamicSharedMemorySize,
                         PSMEM);
    cudaFuncSetAttribute(scores_mma, cudaFuncAttributeMaxDynamicSharedMemorySize,
                         SSMEM);
    cudaFuncSetAttribute(out_mma, cudaFuncAttributeMaxDynamicSharedMemorySize,
                         SSMEM);

    const float* Amats[4] = {input_query, input_key, input_value, loc_vector};
    for (int m = 0; m < 4; m++)
        convA_kernel<<<MK / 1024, 256>>>(Amats[m], Ahi + (size_t)m * MK,
                                         Alo + (size_t)m * MK);
    const float* Wmats[5] = {Wq, Wloc, Wk, Wlk, Wv};
    for (int w = 0; w < 5; w++)
        convW_kernel<<<dim3(HDIM / 32, DDIM / 32), dim3(32, 8)>>>(
            Wmats[w], Whi + (size_t)w * KN, Wlo + (size_t)w * KN);

    ProjParams P;
    const int aidx[5] = {0, 3, 1, 3, 2};
    const float* biases[5] = {bq, bloc, bk, blk, bv};
    float* outs[5] = {q1, q2, lk, kloc, lv};
    for (int g = 0; g < 5; g++) {
        P.Ahi[g]  = Ahi + (size_t)aidx[g] * MK;
        P.Alo[g]  = Alo + (size_t)aidx[g] * MK;
        P.Bhi[g]  = Whi + (size_t)g * KN;
        P.Blo[g]  = Wlo + (size_t)g * KN;
        P.bias[g] = biases[g];
        P.C[g]    = outs[g];
    }
    proj_mma<<<dim3(HDIM / 128, (MTOT + 255) / 256, 5), 512, PSMEM>>>(P);

    qkpack_kernel<<<(BATCH * NSEQ * HDIM / 2 + 255) / 256, 256>>>(param);
    lvT_kernel<<<dim3(HDIM / 32, KOUT / 32, BATCH), dim3(32, 8)>>>();

    scores_mma<<<dim3(2, 2, BATCH), 256, SSMEM>>>();
    softmax_kernel<<<BATCH * NSEQ, 256>>>();
    out_mma<<<dim3(HDIM / 128, 2, BATCH), 256, SSMEM>>>(out);
}

// round 5
// speedup vs baseline: 2.2610x; 1.0232x over previous
#include <cuda_runtime.h>
#include <cuda_bf16.h>
#include <math.h>
#include <stdint.h>

#define BATCH 16
#define NSEQ  200
#define DDIM  2048
#define HDIM  2048
#define MTOT  (BATCH*NSEQ)          // 3200
#define MK    (MTOT*DDIM)
#define KN    (DDIM*HDIM)
#define KCAT  4096                  // scores concatenated K
#define KOUT  224                   // out GEMM K (200 padded)

// ---------------- scratch (device globals) ---------------------------------
__device__ float g_q1[BATCH*NSEQ*HDIM];
__device__ float g_q2[BATCH*NSEQ*HDIM];
__device__ float g_lk[BATCH*NSEQ*HDIM];
__device__ float g_kloc[BATCH*NSEQ*HDIM];
__device__ float g_lv[BATCH*NSEQ*HDIM];
__device__ float g_scores[BATCH*NSEQ*NSEQ];

__device__ __align__(16) __nv_bfloat16 gA_hi[4*MK];
__device__ __align__(16) __nv_bfloat16 gA_lo[4*MK];
__device__ __align__(16) __nv_bfloat16 gW_hi[5*KN];
__device__ __align__(16) __nv_bfloat16 gW_lo[5*KN];

__device__ __align__(16) __nv_bfloat16 gQc_hi[BATCH*NSEQ*KCAT];
__device__ __align__(16) __nv_bfloat16 gQc_lo[BATCH*NSEQ*KCAT];
__device__ __align__(16) __nv_bfloat16 gKc_hi[BATCH*NSEQ*KCAT];
__device__ __align__(16) __nv_bfloat16 gKc_lo[BATCH*NSEQ*KCAT];

__device__ __align__(16) __nv_bfloat16 gAttn_hi[BATCH*NSEQ*KOUT];
__device__ __align__(16) __nv_bfloat16 gAttn_lo[BATCH*NSEQ*KOUT];
__device__ __align__(16) __nv_bfloat16 gLvT_hi[BATCH*HDIM*KOUT];
__device__ __align__(16) __nv_bfloat16 gLvT_lo[BATCH*HDIM*KOUT];

// ============================ helpers ======================================
__device__ __forceinline__ uint32_t smem_u32(const void* p) {
    uint32_t a;
    asm("{ .reg .u64 t; cvta.to.shared.u64 t, %1; cvt.u32.u64 %0, t; }"
        : "=r"(a) : "l"(p));
    return a;
}
__device__ __forceinline__ void cp16(uint32_t dst, const void* src) {
    asm volatile("cp.async.cg.shared.global [%0], [%1], 16;" :: "r"(dst), "l"(src));
}
#define CP_COMMIT() asm volatile("cp.async.commit_group;" ::: "memory")
#define CP_WAIT1()  asm volatile("cp.async.wait_group 1;" ::: "memory")
#define CP_WAIT0()  asm volatile("cp.async.wait_group 0;" ::: "memory")

__device__ __forceinline__ void ldx4(uint32_t addr, uint32_t& r0, uint32_t& r1,
                                     uint32_t& r2, uint32_t& r3) {
    asm volatile("ldmatrix.sync.aligned.m8n8.x4.shared.b16 {%0,%1,%2,%3}, [%4];"
                 : "=r"(r0), "=r"(r1), "=r"(r2), "=r"(r3) : "r"(addr));
}
__device__ __forceinline__ void mma16816(float* c, const uint32_t* a,
                                         const uint32_t* b) {
    asm volatile(
        "mma.sync.aligned.m16n8k16.row.col.f32.bf16.bf16.f32 "
        "{%0,%1,%2,%3}, {%4,%5,%6,%7}, {%8,%9}, {%0,%1,%2,%3};"
        : "+f"(c[0]), "+f"(c[1]), "+f"(c[2]), "+f"(c[3])
        : "r"(a[0]), "r"(a[1]), "r"(a[2]), "r"(a[3]), "r"(b[0]), "r"(b[1]));
}
__device__ __forceinline__ void split_bf16(float x, __nv_bfloat16& h,
                                           __nv_bfloat16& l) {
    h = __float2bfloat16_rn(x);
    l = __float2bfloat16_rn(x - __bfloat162float(h));
}

// =================== conversion kernels (z-batched) ========================
struct ConvAP { const float* src[4]; };
__global__ __launch_bounds__(256) void convA_kernel(ConvAP P)
{
    const int m = blockIdx.z;
    size_t i = ((size_t)blockIdx.x * 256 + threadIdx.x) * 4;
    float4 a = *(const float4*)(P.src[m] + i);
    __nv_bfloat16* hi = gA_hi + (size_t)m * MK;
    __nv_bfloat16* lo = gA_lo + (size_t)m * MK;
    __nv_bfloat16 h0, h1, h2, h3, l0, l1, l2, l3;
    split_bf16(a.x, h0, l0); split_bf16(a.y, h1, l1);
    split_bf16(a.z, h2, l2); split_bf16(a.w, h3, l3);
    ((__nv_bfloat162*)(hi + i))[0] = __nv_bfloat162(h0, h1);
    ((__nv_bfloat162*)(hi + i))[1] = __nv_bfloat162(h2, h3);
    ((__nv_bfloat162*)(lo + i))[0] = __nv_bfloat162(l0, l1);
    ((__nv_bfloat162*)(lo + i))[1] = __nv_bfloat162(l2, l3);
}

struct ConvWP { const float* src[5]; };
__global__ __launch_bounds__(256) void convW_kernel(ConvWP P)
{
    __shared__ float t[32][33];
    const int w  = blockIdx.z;
    const int n0 = blockIdx.x * 32, k0 = blockIdx.y * 32;
    const int tx = threadIdx.x, ty = threadIdx.y;
    const float* W = P.src[w];
    __nv_bfloat16* hi = gW_hi + (size_t)w * KN;
    __nv_bfloat16* lo = gW_lo + (size_t)w * KN;
#pragma unroll
    for (int r = ty; r < 32; r += 8)
        t[r][tx] = W[(size_t)(k0 + r) * HDIM + n0 + tx];
    __syncthreads();
#pragma unroll
    for (int r = ty; r < 32; r += 8) {
        __nv_bfloat16 h, l;
        split_bf16(t[tx][r], h, l);
        size_t off = (size_t)(n0 + r) * DDIM + k0 + tx;
        hi[off] = h;
        lo[off] = l;
    }
}

// =================== HMMA projection GEMM ==================================
// C[3200,2048] = A @ Wt^T + bias.  BM=128 x BN=128, BK=32, 256 thr (2x4 warps),
// warp tile 64x32.  2 CTAs/SM (stage 40KB, double buffered -> 80KB).
struct ProjParams {
    const __nv_bfloat16 *Ahi[5], *Alo[5], *Bhi[5], *Blo[5];
    const float* bias[5];
    float* C[5];
};

#define PSTAGE 40960   // Ahi 10240 | Alo 10240 | Bhi 10240 | Blo 10240
#define PSMEM  (2*PSTAGE)
#define NCHUNK 64

__global__ __launch_bounds__(256, 2) void proj_mma(ProjParams P)
{
    extern __shared__ __align__(128) char smem[];
    const int g  = blockIdx.z;
    const int bn = blockIdx.x * 128;
    const int bm = blockIdx.y * 128;
    const int tid  = threadIdx.x;
    const int lane = tid & 31;
    const int wid  = tid >> 5;
    const int wm = (wid & 1) * 64;
    const int wn = (wid >> 1) * 32;
    const uint32_t sbase = smem_u32(smem);

    const __nv_bfloat16* Ahi = P.Ahi[g];
    const __nv_bfloat16* Alo = P.Alo[g];
    const __nv_bfloat16* Bhi = P.Bhi[g];
    const __nv_bfloat16* Blo = P.Blo[g];
    const float* bias = P.bias[g];
    float* C = P.C[g];

    float acc[4][4][4];
#pragma unroll
    for (int i = 0; i < 4; i++)
#pragma unroll
        for (int j = 0; j < 4; j++)
#pragma unroll
            for (int k = 0; k < 4; k++) acc[i][j][k] = 0.f;

    auto load_chunk = [&](int chunk, int s) {
        const int k0 = chunk * 32;
        const uint32_t sb = sbase + s * PSTAGE;
#pragma unroll
        for (int u = 0; u < 8; u++) {
            int idx = u * 256 + tid;
            int region = idx >> 9;             // 0:Ahi 1:Alo 2:Bhi 3:Blo
            int i2 = idx & 511;
            int r = i2 >> 2, c = i2 & 3;
            const __nv_bfloat16* base =
                (region == 0) ? Ahi : (region == 1) ? Alo
                              : (region == 2) ? Bhi : Blo;
            int row = ((region < 2) ? bm : bn) + r;
            cp16(sb + region * 10240 + r * 80 + c * 16,
                 base + (size_t)row * DDIM + k0 + c * 8);
        }
    };

    load_chunk(0, 0);
    CP_COMMIT();

    const int lrow = (lane & 7) + ((lane >> 3) & 1) * 8;
    const int lcol = (lane >> 4) * 8;

    for (int it = 0; it < NCHUNK; it++) {
        const int cur = it & 1;
        if (it + 1 < NCHUNK) {
            load_chunk(it + 1, (it + 1) & 1);
            CP_COMMIT();
            CP_WAIT1();
        } else {
            CP_WAIT0();
        }
        __syncthreads();

        const uint32_t sb = sbase + cur * PSTAGE;
#pragma unroll
        for (int ks = 0; ks < 2; ks++) {
            const int colb = (ks * 16 + lcol) * 2;
            uint32_t Bh[4][2], Bl[4][2];
#pragma unroll
            for (int half = 0; half < 2; half++) {
                const int nrow = wn + half * 16 + lrow;
                uint32_t r0, r1, r2, r3;
                ldx4(sb + 20480 + nrow * 80 + colb, r0, r1, r2, r3);
                Bh[half * 2 + 0][0] = r0; Bh[half * 2 + 1][0] = r1;
                Bh[half * 2 + 0][1] = r2; Bh[half * 2 + 1][1] = r3;
                ldx4(sb + 30720 + nrow * 80 + colb, r0, r1, r2, r3);
                Bl[half * 2 + 0][0] = r0; Bl[half * 2 + 1][0] = r1;
                Bl[half * 2 + 0][1] = r2; Bl[half * 2 + 1][1] = r3;
            }
#pragma unroll
            for (int p = 0; p < 2; p++) {
                uint32_t ah[2][4], al[2][4];
#pragma unroll
                for (int m2 = 0; m2 < 2; m2++) {
                    const int mrow = wm + (p * 2 + m2) * 16 + lrow;
                    ldx4(sb + mrow * 80 + colb,
                         ah[m2][0], ah[m2][1], ah[m2][2], ah[m2][3]);
                    ldx4(sb + 10240 + mrow * 80 + colb,
                         al[m2][0], al[m2][1], al[m2][2], al[m2][3]);
                }
#pragma unroll
                for (int m2 = 0; m2 < 2; m2++)
#pragma unroll
                    for (int nj = 0; nj < 4; nj++)
                        mma16816(acc[p * 2 + m2][nj], ah[m2], Bh[nj]);
#pragma unroll
                for (int m2 = 0; m2 < 2; m2++)
#pragma unroll
                    for (int nj = 0; nj < 4; nj++)
                        mma16816(acc[p * 2 + m2][nj], ah[m2], Bl[nj]);
#pragma unroll
                for (int m2 = 0; m2 < 2; m2++)
#pragma unroll
                    for (int nj = 0; nj < 4; nj++)
                        mma16816(acc[p * 2 + m2][nj], al[m2], Bh[nj]);
            }
        }
        __syncthreads();
    }

    const int gq = lane >> 2;
    const int tq = lane & 3;
#pragma unroll
    for (int mi = 0; mi < 4; mi++) {
#pragma unroll
        for (int nj = 0; nj < 4; nj++) {
            int col = bn + wn + nj * 8 + tq * 2;
            float b0 = __ldg(bias + col);
            float b1 = __ldg(bias + col + 1);
            int row0 = bm + wm + mi * 16 + gq;
            *(float2*)(C + (size_t)row0 * HDIM + col) =
                make_float2(acc[mi][nj][0] + b0, acc[mi][nj][1] + b1);
            *(float2*)(C + (size_t)(row0 + 8) * HDIM + col) =
                make_float2(acc[mi][nj][2] + b0, acc[mi][nj][3] + b1);
        }
    }
}

// =============== qk pack: build concat bf16 hi/lo operands =================
__global__ __launch_bounds__(256) void qkpack_kernel(const float* __restrict__ param)
{
    size_t i2 = (size_t)blockIdx.x * 256 + threadIdx.x;
    if (i2 >= (size_t)BATCH * NSEQ * HDIM / 2) return;
    size_t i = i2 * 2;
    size_t bn = i / HDIM;
    int    h  = (int)(i % HDIM);
    size_t base = bn * KCAT + h;

    float2 lq = *(const float2*)(g_q1 + i);
    float2 ll = *(const float2*)(g_q2 + i);
    float2 pp = *(const float2*)(param + i);
    float2 lk = *(const float2*)(g_lk + i);
    float2 kl = *(const float2*)(g_kloc + i);

    __nv_bfloat16 h0, l0, h1, l1;
    split_bf16(lq.x + pp.x, h0, l0); split_bf16(lq.y + pp.y, h1, l1);
    *(__nv_bfloat162*)(gQc_hi + base) = __nv_bfloat162(h0, h1);
    *(__nv_bfloat162*)(gQc_lo + base) = __nv_bfloat162(l0, l1);
    split_bf16(lq.x + ll.x, h0, l0); split_bf16(lq.y + ll.y, h1, l1);
    *(__nv_bfloat162*)(gQc_hi + base + DDIM) = __nv_bfloat162(h0, h1);
    *(__nv_bfloat162*)(gQc_lo + base + DDIM) = __nv_bfloat162(l0, l1);
    split_bf16(lk.x, h0, l0); split_bf16(lk.y, h1, l1);
    *(__nv_bfloat162*)(gKc_hi + base) = __nv_bfloat162(h0, h1);
    *(__nv_bfloat162*)(gKc_lo + base) = __nv_bfloat162(l0, l1);
    split_bf16(kl.x, h0, l0); split_bf16(kl.y, h1, l1);
    *(__nv_bfloat162*)(gKc_hi + base + DDIM) = __nv_bfloat162(h0, h1);
    *(__nv_bfloat162*)(gKc_lo + base + DDIM) = __nv_bfloat162(l0, l1);
}

// =================== HMMA scores GEMM ======================================
#define SSTAGE 40960
#define SSMEM  (2*SSTAGE)
#define SNCHUNK 128

__global__ __launch_bounds__(256, 2) void scores_mma()
{
    extern __shared__ __align__(128) char smem[];
    const int b  = blockIdx.z;
    const int m0 = blockIdx.x * 128;
    const int n0 = blockIdx.y * 128;
    const int tid  = threadIdx.x;
    const int lane = tid & 31;
    const int wid  = tid >> 5;
    const int wm = (wid & 1) * 64;
    const int wn = (wid >> 1) * 32;
    const uint32_t sbase = smem_u32(smem);

    const size_t bo = (size_t)b * NSEQ * KCAT;
    const __nv_bfloat16* Ahi = gQc_hi + bo;
    const __nv_bfloat16* Alo = gQc_lo + bo;
    const __nv_bfloat16* Bhi = gKc_hi + bo;
    const __nv_bfloat16* Blo = gKc_lo + bo;

    float acc[4][4][4];
#pragma unroll
    for (int i = 0; i < 4; i++)
#pragma unroll
        for (int j = 0; j < 4; j++)
#pragma unroll
            for (int k = 0; k < 4; k++) acc[i][j][k] = 0.f;

    auto load_chunk = [&](int chunk, int s) {
        const int k0 = chunk * 32;
        const uint32_t sb = sbase + s * SSTAGE;
#pragma unroll
        for (int u = 0; u < 8; u++) {
            int idx = u * 256 + tid;
            int region = idx >> 9;
            int i2 = idx & 511;
            int r = i2 >> 2, c = i2 & 3;
            const __nv_bfloat16* base =
                (region == 0) ? Ahi : (region == 1) ? Alo
                              : (region == 2) ? Bhi : Blo;
            int row = ((region < 2) ? n0 : m0) + r;
            if (row > NSEQ - 1) row = NSEQ - 1;
            cp16(sb + region * 10240 + r * 80 + c * 16,
                 base + (size_t)row * KCAT + k0 + c * 8);
        }
    };

    load_chunk(0, 0);
    CP_COMMIT();

    const int lrow = (lane & 7) + ((lane >> 3) & 1) * 8;
    const int lcol = (lane >> 4) * 8;

    for (int it = 0; it < SNCHUNK; it++) {
        const int cur = it & 1;
        if (it + 1 < SNCHUNK) {
            load_chunk(it + 1, (it + 1) & 1);
            CP_COMMIT();
            CP_WAIT1();
        } else {
            CP_WAIT0();
        }
        __syncthreads();

        const uint32_t sb = sbase + cur * SSTAGE;
#pragma unroll
        for (int ks = 0; ks < 2; ks++) {
            const int colb = (ks * 16 + lcol) * 2;
            uint32_t Bh[4][2], Bl[4][2];
#pragma unroll
            for (int half = 0; half < 2; half++) {
                const int nrow = wn + half * 16 + lrow;
                uint32_t r0, r1, r2, r3;
                ldx4(sb + 20480 + nrow * 80 + colb, r0, r1, r2, r3);
                Bh[half * 2 + 0][0] = r0; Bh[half * 2 + 1][0] = r1;
                Bh[half * 2 + 0][1] = r2; Bh[half * 2 + 1][1] = r3;
                ldx4(sb + 30720 + nrow * 80 + colb, r0, r1, r2, r3);
                Bl[half * 2 + 0][0] = r0; Bl[half * 2 + 1][0] = r1;
                Bl[half * 2 + 0][1] = r2; Bl[half * 2 + 1][1] = r3;
            }
#pragma unroll
            for (int p = 0; p < 2; p++) {
                uint32_t ah[2][4], al[2][4];
#pragma unroll
                for (int m2 = 0; m2 < 2; m2++) {
                    const int mrow = wm + (p * 2 + m2) * 16 + lrow;
                    ldx4(sb + mrow * 80 + colb,
                         ah[m2][0], ah[m2][1], ah[m2][2], ah[m2][3]);
                    ldx4(sb + 10240 + mrow * 80 + colb,
                         al[m2][0], al[m2][1], al[m2][2], al[m2][3]);
                }
#pragma unroll
                for (int m2 = 0; m2 < 2; m2++)
#pragma unroll
                    for (int nj = 0; nj < 4; nj++)
                        mma16816(acc[p * 2 + m2][nj], ah[m2], Bh[nj]);
#pragma unroll
                for (int m2 = 0; m2 < 2; m2++)
#pragma unroll
                    for (int nj = 0; nj < 4; nj++)
                        mma16816(acc[p * 2 + m2][nj], ah[m2], Bl[nj]);
#pragma unroll
                for (int m2 = 0; m2 < 2; m2++)
#pragma unroll
                    for (int nj = 0; nj < 4; nj++)
                        mma16816(acc[p * 2 + m2][nj], al[m2], Bh[nj]);
            }
        }
        __syncthreads();
    }

    float* sc = g_scores + (size_t)b * NSEQ * NSEQ;
    const int gq = lane >> 2;
    const int tq = lane & 3;
#pragma unroll
    for (int mi = 0; mi < 4; mi++) {
#pragma unroll
        for (int nj = 0; nj < 4; nj++) {
            int col = m0 + wn + nj * 8 + tq * 2;
            if (col >= NSEQ) continue;
            int row0 = n0 + wm + mi * 16 + gq;
            if (row0 < NSEQ)
                *(float2*)(sc + (size_t)row0 * NSEQ + col) =
                    make_float2(acc[mi][nj][0], acc[mi][nj][1]);
            int row1 = row0 + 8;
            if (row1 < NSEQ)
                *(float2*)(sc + (size_t)row1 * NSEQ + col) =
                    make_float2(acc[mi][nj][2], acc[mi][nj][3]);
        }
    }
}

// ---------------- softmax -> bf16 hi/lo attn (padded to 224) --------------
__global__ __launch_bounds__(256) void softmax_kernel()
{
    const int row = blockIdx.x;
    float* s = g_scores + (size_t)row * NSEQ;
    const int tid = threadIdx.x;
    __shared__ float red[8];

    float v = (tid < NSEQ) ? s[tid] : -3.0e38f;
#pragma unroll
    for (int o = 16; o; o >>= 1) v = fmaxf(v, __shfl_xor_sync(0xffffffffu, v, o));
    if ((tid & 31) == 0) red[tid >> 5] = v;
    __syncthreads();
    float vmax = red[0];
#pragma unroll
    for (int w = 1; w < 8; w++) vmax = fmaxf(vmax, red[w]);

    const float scale = 0.02209708691207961f;
    float e = (tid < NSEQ) ? __expf((s[tid] - vmax) * scale) : 0.f;
    float sum = e;
#pragma unroll
    for (int o = 16; o; o >>= 1) sum += __shfl_xor_sync(0xffffffffu, sum, o);
    __syncthreads();
    if ((tid & 31) == 0) red[tid >> 5] = sum;
    __syncthreads();
    float tot = 0.f;
#pragma unroll
    for (int w = 0; w < 8; w++) tot += red[w];

    if (tid < KOUT) {
        float a = (tid < NSEQ) ? e / tot : 0.f;
        __nv_bfloat16 h, l;
        split_bf16(a, h, l);
        gAttn_hi[(size_t)row * KOUT + tid] = h;
        gAttn_lo[(size_t)row * KOUT + tid] = l;
    }
}

// ---------------- lv transpose + split: lvT[b][o][m] ----------------------
__global__ __launch_bounds__(256) void lvT_kernel()
{
    __shared__ float t[32][33];
    const int b  = blockIdx.z;
    const int o0 = blockIdx.x * 32;
    const int m0 = blockIdx.y * 32;
    const int tx = threadIdx.x, ty = threadIdx.y;
    const float* lv = g_lv + (size_t)b * NSEQ * HDIM;
#pragma unroll
    for (int r = ty; r < 32; r += 8) {
        int m = m0 + r;
        t[r][tx] = (m < NSEQ) ? lv[(size_t)m * HDIM + o0 + tx] : 0.f;
    }
    __syncthreads();
#pragma unroll
    for (int r = ty; r < 32; r += 8) {
        __nv_bfloat16 h, l;
        split_bf16(t[tx][r], h, l);
        size_t off = ((size_t)b * HDIM + o0 + r) * KOUT + m0 + tx;
        gLvT_hi[off] = h;
        gLvT_lo[off] = l;
    }
}

// =================== HMMA output GEMM ======================================
#define ONCHUNK 7

__global__ __launch_bounds__(256, 2) void out_mma(float* __restrict__ out)
{
    extern __shared__ __align__(128) char smem[];
    const int b  = blockIdx.z;
    const int o0 = blockIdx.x * 128;
    const int n0 = blockIdx.y * 128;
    const int tid  = threadIdx.x;
    const int lane = tid & 31;
    const int wid  = tid >> 5;
    const int wm = (wid & 1) * 64;
    const int wn = (wid >> 1) * 32;
    const uint32_t sbase = smem_u32(smem);

    const __nv_bfloat16* Ahi = gAttn_hi + (size_t)b * NSEQ * KOUT;
    const __nv_bfloat16* Alo = gAttn_lo + (size_t)b * NSEQ * KOUT;
    const __nv_bfloat16* Bhi = gLvT_hi + (size_t)b * HDIM * KOUT;
    const __nv_bfloat16* Blo = gLvT_lo + (size_t)b * HDIM * KOUT;

    float acc[4][4][4];
#pragma unroll
    for (int i = 0; i < 4; i++)
#pragma unroll
        for (int j = 0; j < 4; j++)
#pragma unroll
            for (int k = 0; k < 4; k++) acc[i][j][k] = 0.f;

    auto load_chunk = [&](int chunk, int s) {
        const int k0 = chunk * 32;
        const uint32_t sb = sbase + s * SSTAGE;
#pragma unroll
        for (int u = 0; u < 8; u++) {
            int idx = u * 256 + tid;
            int region = idx >> 9;
            int i2 = idx & 511;
            int r = i2 >> 2, c = i2 & 3;
            const __nv_bfloat16* base;
            size_t off;
            if (region < 2) {
                int row = n0 + r; if (row > NSEQ - 1) row = NSEQ - 1;
                base = region ? Alo : Ahi;
                off = (size_t)row * KOUT + k0 + c * 8;
            } else {
                base = (region == 3) ? Blo : Bhi;
                off = (size_t)(o0 + r) * KOUT + k0 + c * 8;
            }
            cp16(sb + region * 10240 + r * 80 + c * 16, base + off);
        }
    };

    load_chunk(0, 0);
    CP_COMMIT();

    const int lrow = (lane & 7) + ((lane >> 3) & 1) * 8;
    const int lcol = (lane >> 4) * 8;

    for (int it = 0; it < ONCHUNK; it++) {
        const int cur = it & 1;
        if (it + 1 < ONCHUNK) {
            load_chunk(it + 1, (it + 1) & 1);
            CP_COMMIT();
            CP_WAIT1();
        } else {
            CP_WAIT0();
        }
        __syncthreads();

        const uint32_t sb = sbase + cur * SSTAGE;
#pragma unroll
        for (int ks = 0; ks < 2; ks++) {
            const int colb = (ks * 16 + lcol) * 2;
            uint32_t Bh[4][2], Bl[4][2];
#pragma unroll
            for (int half = 0; half < 2; half++) {
                const int nrow = wn + half * 16 + lrow;
                uint32_t r0, r1, r2, r3;
                ldx4(sb + 20480 + nrow * 80 + colb, r0, r1, r2, r3);
                Bh[half * 2 + 0][0] = r0; Bh[half * 2 + 1][0] = r1;
                Bh[half * 2 + 0][1] = r2; Bh[half * 2 + 1][1] = r3;
                ldx4(sb + 30720 + nrow * 80 + colb, r0, r1, r2, r3);
                Bl[half * 2 + 0][0] = r0; Bl[half * 2 + 1][0] = r1;
                Bl[half * 2 + 0][1] = r2; Bl[half * 2 + 1][1] = r3;
            }
#pragma unroll
            for (int p = 0; p < 2; p++) {
                uint32_t ah[2][4], al[2][4];
#pragma unroll
                for (int m2 = 0; m2 < 2; m2++) {
                    const int mrow = wm + (p * 2 + m2) * 16 + lrow;
                    ldx4(sb + mrow * 80 + colb,
                         ah[m2][0], ah[m2][1], ah[m2][2], ah[m2][3]);
                    ldx4(sb + 10240 + mrow * 80 + colb,
                         al[m2][0], al[m2][1], al[m2][2], al[m2][3]);
                }
#pragma unroll
                for (int m2 = 0; m2 < 2; m2++)
#pragma unroll
                    for (int nj = 0; nj < 4; nj++)
                        mma16816(acc[p * 2 + m2][nj], ah[m2], Bh[nj]);
#pragma unroll
                for (int m2 = 0; m2 < 2; m2++)
#pragma unroll
                    for (int nj = 0; nj < 4; nj++)
                        mma16816(acc[p * 2 + m2][nj], ah[m2], Bl[nj]);
#pragma unroll
                for (int m2 = 0; m2 < 2; m2++)
#pragma unroll
                    for (int nj = 0; nj < 4; nj++)
                        mma16816(acc[p * 2 + m2][nj], al[m2], Bh[nj]);
            }
        }
        __syncthreads();
    }

    const int gq = lane >> 2;
    const int tq = lane & 3;
#pragma unroll
    for (int mi = 0; mi < 4; mi++) {
#pragma unroll
        for (int nj = 0; nj < 4; nj++) {
            int col = o0 + wn + nj * 8 + tq * 2;
            int row0 = n0 + wm + mi * 16 + gq;
            if (row0 < NSEQ)
                *(float2*)(out + ((size_t)b * NSEQ + row0) * HDIM + col) =
                    make_float2(acc[mi][nj][0], acc[mi][nj][1]);
            int row1 = row0 + 8;
            if (row1 < NSEQ)
                *(float2*)(out + ((size_t)b * NSEQ + row1) * HDIM + col) =
                    make_float2(acc[mi][nj][2], acc[mi][nj][3]);
        }
    }
}

// ---------------------------------------------------------------------------
extern "C" void kernel_launch(void* const* d_in, const int* in_sizes, int n_in,
                              void* d_out, int out_size)
{
    const float* input_query = (const float*)d_in[0];
    const float* input_key   = (const float*)d_in[1];
    const float* input_value = (const float*)d_in[2];
    const float* loc_vector  = (const float*)d_in[3];
    const float* Wq   = (const float*)d_in[4];
    const float* bq   = (const float*)d_in[5];
    const float* Wk   = (const float*)d_in[6];
    const float* bk   = (const float*)d_in[7];
    const float* Wv   = (const float*)d_in[8];
    const float* bv   = (const float*)d_in[9];
    const float* Wloc = (const float*)d_in[10];
    const float* bloc = (const float*)d_in[11];
    const float* Wlk  = (const float*)d_in[12];
    const float* blk  = (const float*)d_in[13];
    const float* param = (const float*)d_in[14];
    float* out = (float*)d_out;

    float *q1, *q2, *lk, *kloc, *lv;
    cudaGetSymbolAddress((void**)&q1,   g_q1);
    cudaGetSymbolAddress((void**)&q2,   g_q2);
    cudaGetSymbolAddress((void**)&lk,   g_lk);
    cudaGetSymbolAddress((void**)&kloc, g_kloc);
    cudaGetSymbolAddress((void**)&lv,   g_lv);

    __nv_bfloat16 *Ahi, *Alo, *Whi, *Wlo;
    cudaGetSymbolAddress((void**)&Ahi, gA_hi);
    cudaGetSymbolAddress((void**)&Alo, gA_lo);
    cudaGetSymbolAddress((void**)&Whi, gW_hi);
    cudaGetSymbolAddress((void**)&Wlo, gW_lo);

    cudaFuncSetAttribute(proj_mma, cudaFuncAttributeMaxDynamicSharedMemorySize,
                         PSMEM);
    cudaFuncSetAttribute(scores_mma, cudaFuncAttributeMaxDynamicSharedMemorySize,
                         SSMEM);
    cudaFuncSetAttribute(out_mma, cudaFuncAttributeMaxDynamicSharedMemorySize,
                         SSMEM);

    ConvAP CA;
    CA.src[0] = input_query; CA.src[1] = input_key;
    CA.src[2] = input_value; CA.src[3] = loc_vector;
    convA_kernel<<<dim3(MK / 1024, 1, 4), 256>>>(CA);

    ConvWP CW;
    CW.src[0] = Wq; CW.src[1] = Wloc; CW.src[2] = Wk; CW.src[3] = Wlk; CW.src[4] = Wv;
    convW_kernel<<<dim3(HDIM / 32, DDIM / 32, 5), dim3(32, 8)>>>(CW);

    ProjParams P;
    const int aidx[5] = {0, 3, 1, 3, 2};
    const float* biases[5] = {bq, bloc, bk, blk, bv};
    float* outs[5] = {q1, q2, lk, kloc, lv};
    for (int g = 0; g < 5; g++) {
        P.Ahi[g]  = Ahi + (size_t)aidx[g] * MK;
        P.Alo[g]  = Alo + (size_t)aidx[g] * MK;
        P.Bhi[g]  = Whi + (size_t)g * KN;
        P.Blo[g]  = Wlo + (size_t)g * KN;
        P.bias[g] = biases[g];
        P.C[g]    = outs[g];
    }
    proj_mma<<<dim3(HDIM / 128, MTOT / 128, 5), 256, PSMEM>>>(P);

    qkpack_kernel<<<(BATCH * NSEQ * HDIM / 2 + 255) / 256, 256>>>(param);
    lvT_kernel<<<dim3(HDIM / 32, KOUT / 32, BATCH), dim3(32, 8)>>>();

    scores_mma<<<dim3(2, 2, BATCH), 256, SSMEM>>>();
    softmax_kernel<<<BATCH * NSEQ, 256>>>();
    out_mma<<<dim3(HDIM / 128, 2, BATCH), 256, SSMEM>>>(out);
}

// round 6
// speedup vs baseline: 3.1307x; 1.3846x over previous
#include <cuda_runtime.h>
#include <cuda_bf16.h>
#include <math.h>
#include <stdint.h>

#define BATCH 16
#define NSEQ  200
#define DDIM  2048
#define HDIM  2048
#define MTOT  (BATCH*NSEQ)          // 3200
#define MK    (MTOT*DDIM)
#define KN    (DDIM*HDIM)
#define KCAT  4096                  // scores concatenated K
#define KOUT  224                   // out GEMM K (200 padded)

// ---------------- scratch (device globals) ---------------------------------
__device__ float g_q1[BATCH*NSEQ*HDIM];
__device__ float g_q2[BATCH*NSEQ*HDIM];
__device__ float g_lk[BATCH*NSEQ*HDIM];
__device__ float g_kloc[BATCH*NSEQ*HDIM];
__device__ float g_lv[BATCH*NSEQ*HDIM];
__device__ float g_scores[BATCH*NSEQ*NSEQ];

// tf32-rounded fp32 operands for projections.  A: 0=query,1=key,2=value,3=loc
__device__ __align__(16) float gAt[4*MK];
// W transposed [N][K]: 0=Wq,1=Wloc,2=Wk,3=Wlk,4=Wv
__device__ __align__(16) float gWt[5*KN];

// scores/out bf16-split operands
__device__ __align__(16) __nv_bfloat16 gQc_hi[BATCH*NSEQ*KCAT];
__device__ __align__(16) __nv_bfloat16 gQc_lo[BATCH*NSEQ*KCAT];
__device__ __align__(16) __nv_bfloat16 gKc_hi[BATCH*NSEQ*KCAT];
__device__ __align__(16) __nv_bfloat16 gKc_lo[BATCH*NSEQ*KCAT];
__device__ __align__(16) __nv_bfloat16 gAttn_hi[BATCH*NSEQ*KOUT];
__device__ __align__(16) __nv_bfloat16 gAttn_lo[BATCH*NSEQ*KOUT];
__device__ __align__(16) __nv_bfloat16 gLvT_hi[BATCH*HDIM*KOUT];
__device__ __align__(16) __nv_bfloat16 gLvT_lo[BATCH*HDIM*KOUT];

// ============================ helpers ======================================
__device__ __forceinline__ uint32_t smem_u32(const void* p) {
    uint32_t a;
    asm("{ .reg .u64 t; cvta.to.shared.u64 t, %1; cvt.u32.u64 %0, t; }"
        : "=r"(a) : "l"(p));
    return a;
}
__device__ __forceinline__ void cp16(uint32_t dst, const void* src) {
    asm volatile("cp.async.cg.shared.global [%0], [%1], 16;" :: "r"(dst), "l"(src));
}
#define CP_COMMIT() asm volatile("cp.async.commit_group;" ::: "memory")
#define CP_WAIT1()  asm volatile("cp.async.wait_group 1;" ::: "memory")
#define CP_WAIT0()  asm volatile("cp.async.wait_group 0;" ::: "memory")

__device__ __forceinline__ void ldx4(uint32_t addr, uint32_t& r0, uint32_t& r1,
                                     uint32_t& r2, uint32_t& r3) {
    asm volatile("ldmatrix.sync.aligned.m8n8.x4.shared.b16 {%0,%1,%2,%3}, [%4];"
                 : "=r"(r0), "=r"(r1), "=r"(r2), "=r"(r3) : "r"(addr));
}
__device__ __forceinline__ void mma16816(float* c, const uint32_t* a,
                                         const uint32_t* b) {
    asm volatile(
        "mma.sync.aligned.m16n8k16.row.col.f32.bf16.bf16.f32 "
        "{%0,%1,%2,%3}, {%4,%5,%6,%7}, {%8,%9}, {%0,%1,%2,%3};"
        : "+f"(c[0]), "+f"(c[1]), "+f"(c[2]), "+f"(c[3])
        : "r"(a[0]), "r"(a[1]), "r"(a[2]), "r"(a[3]), "r"(b[0]), "r"(b[1]));
}
__device__ __forceinline__ void mma_tf32(float* c, const uint32_t* a,
                                         const uint32_t* b) {
    asm volatile(
        "mma.sync.aligned.m16n8k8.row.col.f32.tf32.tf32.f32 "
        "{%0,%1,%2,%3}, {%4,%5,%6,%7}, {%8,%9}, {%0,%1,%2,%3};"
        : "+f"(c[0]), "+f"(c[1]), "+f"(c[2]), "+f"(c[3])
        : "r"(a[0]), "r"(a[1]), "r"(a[2]), "r"(a[3]), "r"(b[0]), "r"(b[1]));
}
__device__ __forceinline__ float f2tf32(float x) {
    uint32_t r;
    asm("cvt.rna.tf32.f32 %0, %1;" : "=r"(r) : "f"(x));
    return __uint_as_float(r);
}
__device__ __forceinline__ void split_bf16(float x, __nv_bfloat16& h,
                                           __nv_bfloat16& l) {
    h = __float2bfloat16_rn(x);
    l = __float2bfloat16_rn(x - __bfloat162float(h));
}

// =================== conversion kernels (tf32 round) =======================
struct ConvAP { const float* src[4]; };
__global__ __launch_bounds__(256) void convA_kernel(ConvAP P)
{
    const int m = blockIdx.z;
    size_t i = ((size_t)blockIdx.x * 256 + threadIdx.x) * 4;
    float4 a = *(const float4*)(P.src[m] + i);
    a.x = f2tf32(a.x); a.y = f2tf32(a.y);
    a.z = f2tf32(a.z); a.w = f2tf32(a.w);
    *(float4*)(gAt + (size_t)m * MK + i) = a;
}

struct ConvWP { const float* src[5]; };
__global__ __launch_bounds__(256) void convW_kernel(ConvWP P)
{
    __shared__ float t[32][33];
    const int w  = blockIdx.z;
    const int n0 = blockIdx.x * 32, k0 = blockIdx.y * 32;
    const int tx = threadIdx.x, ty = threadIdx.y;
    const float* W = P.src[w];
    float* Wt = gWt + (size_t)w * KN;
#pragma unroll
    for (int r = ty; r < 32; r += 8)
        t[r][tx] = W[(size_t)(k0 + r) * HDIM + n0 + tx];
    __syncthreads();
#pragma unroll
    for (int r = ty; r < 32; r += 8)
        Wt[(size_t)(n0 + r) * DDIM + k0 + tx] = f2tf32(t[tx][r]);
}

// =================== TF32 projection GEMM ==================================
// C[3200,2048] = A @ Wt^T + bias.  BM=128 x BN=128, BK=32, 256 thr (2x4 warps),
// warp tile 64x32, single-pass tf32 (m16n8k8).
struct ProjParams {
    const float *A[5], *B[5], *bias[5];
    float* C[5];
};

#define TPITCH  36                   // floats per smem row (bank-safe)
#define TROW    (TPITCH*4)           // 144 B
#define TSTAGE  (2*128*TROW)         // A 18432 + B 18432 = 36864
#define TSMEM   (2*TSTAGE)           // 73728
#define NCHUNK  64

__global__ __launch_bounds__(256, 2) void proj_mma(ProjParams P)
{
    extern __shared__ __align__(128) char smem[];
    const int g  = blockIdx.z;
    const int bn = blockIdx.x * 128;
    const int bm = blockIdx.y * 128;
    const int tid  = threadIdx.x;
    const int lane = tid & 31;
    const int wid  = tid >> 5;
    const int wm = (wid & 1) * 64;
    const int wn = (wid >> 1) * 32;
    const uint32_t sbase = smem_u32(smem);
    float* fs = reinterpret_cast<float*>(smem);

    const float* A = P.A[g];
    const float* B = P.B[g];
    const float* bias = P.bias[g];
    float* C = P.C[g];

    float acc[4][4][4];
#pragma unroll
    for (int i = 0; i < 4; i++)
#pragma unroll
        for (int j = 0; j < 4; j++)
#pragma unroll
            for (int k = 0; k < 4; k++) acc[i][j][k] = 0.f;

    // 2048 cp16 per chunk: A 128 rows x 8, B 128 rows x 8 -> 8/thread
    auto load_chunk = [&](int chunk, int s) {
        const int k0 = chunk * 32;
        const uint32_t sb = sbase + s * TSTAGE;
#pragma unroll
        for (int u = 0; u < 8; u++) {
            int idx = u * 256 + tid;
            int region = idx >> 10;            // 0:A 1:B
            int i2 = idx & 1023;
            int r = i2 >> 3, c = i2 & 7;
            const float* src = region
                ? B + (size_t)(bn + r) * DDIM + k0 + c * 4
                : A + (size_t)(bm + r) * DDIM + k0 + c * 4;
            cp16(sb + region * (128 * TROW) + r * TROW + c * 16, src);
        }
    };

    load_chunk(0, 0);
    CP_COMMIT();

    const int gq = lane >> 2;          // 0..7
    const int tq = lane & 3;           // 0..3

    for (int it = 0; it < NCHUNK; it++) {
        const int cur = it & 1;
        if (it + 1 < NCHUNK) {
            load_chunk(it + 1, (it + 1) & 1);
            CP_COMMIT();
            CP_WAIT1();
        } else {
            CP_WAIT0();
        }
        __syncthreads();

        const float* As = fs + cur * (TSTAGE / 4);
        const float* Bs = As + 128 * TPITCH;
#pragma unroll
        for (int ks = 0; ks < 4; ks++) {
            const int kk = ks * 8;
            uint32_t bfr[4][2];
#pragma unroll
            for (int nj = 0; nj < 4; nj++) {
                const int brow = wn + nj * 8 + gq;
                bfr[nj][0] = __float_as_uint(Bs[brow * TPITCH + kk + tq]);
                bfr[nj][1] = __float_as_uint(Bs[brow * TPITCH + kk + tq + 4]);
            }
#pragma unroll
            for (int mi = 0; mi < 4; mi++) {
                const int ar = wm + mi * 16;
                uint32_t afr[4];
                afr[0] = __float_as_uint(As[(ar + gq) * TPITCH + kk + tq]);
                afr[1] = __float_as_uint(As[(ar + 8 + gq) * TPITCH + kk + tq]);
                afr[2] = __float_as_uint(As[(ar + gq) * TPITCH + kk + tq + 4]);
                afr[3] = __float_as_uint(As[(ar + 8 + gq) * TPITCH + kk + tq + 4]);
#pragma unroll
                for (int nj = 0; nj < 4; nj++)
                    mma_tf32(acc[mi][nj], afr, bfr[nj]);
            }
        }
        __syncthreads();
    }

#pragma unroll
    for (int mi = 0; mi < 4; mi++) {
#pragma unroll
        for (int nj = 0; nj < 4; nj++) {
            int col = bn + wn + nj * 8 + tq * 2;
            float b0 = __ldg(bias + col);
            float b1 = __ldg(bias + col + 1);
            int row0 = bm + wm + mi * 16 + gq;
            *(float2*)(C + (size_t)row0 * HDIM + col) =
                make_float2(acc[mi][nj][0] + b0, acc[mi][nj][1] + b1);
            *(float2*)(C + (size_t)(row0 + 8) * HDIM + col) =
                make_float2(acc[mi][nj][2] + b0, acc[mi][nj][3] + b1);
        }
    }
}

// =============== qk pack: build concat bf16 hi/lo operands =================
__global__ __launch_bounds__(256) void qkpack_kernel(const float* __restrict__ param)
{
    size_t i2 = (size_t)blockIdx.x * 256 + threadIdx.x;
    if (i2 >= (size_t)BATCH * NSEQ * HDIM / 2) return;
    size_t i = i2 * 2;
    size_t bn = i / HDIM;
    int    h  = (int)(i % HDIM);
    size_t base = bn * KCAT + h;

    float2 lq = *(const float2*)(g_q1 + i);
    float2 ll = *(const float2*)(g_q2 + i);
    float2 pp = *(const float2*)(param + i);
    float2 lk = *(const float2*)(g_lk + i);
    float2 kl = *(const float2*)(g_kloc + i);

    __nv_bfloat16 h0, l0, h1, l1;
    split_bf16(lq.x + pp.x, h0, l0); split_bf16(lq.y + pp.y, h1, l1);
    *(__nv_bfloat162*)(gQc_hi + base) = __nv_bfloat162(h0, h1);
    *(__nv_bfloat162*)(gQc_lo + base) = __nv_bfloat162(l0, l1);
    split_bf16(lq.x + ll.x, h0, l0); split_bf16(lq.y + ll.y, h1, l1);
    *(__nv_bfloat162*)(gQc_hi + base + DDIM) = __nv_bfloat162(h0, h1);
    *(__nv_bfloat162*)(gQc_lo + base + DDIM) = __nv_bfloat162(l0, l1);
    split_bf16(lk.x, h0, l0); split_bf16(lk.y, h1, l1);
    *(__nv_bfloat162*)(gKc_hi + base) = __nv_bfloat162(h0, h1);
    *(__nv_bfloat162*)(gKc_lo + base) = __nv_bfloat162(l0, l1);
    split_bf16(kl.x, h0, l0); split_bf16(kl.y, h1, l1);
    *(__nv_bfloat162*)(gKc_hi + base + DDIM) = __nv_bfloat162(h0, h1);
    *(__nv_bfloat162*)(gKc_lo + base + DDIM) = __nv_bfloat162(l0, l1);
}

// =================== HMMA scores GEMM ======================================
#define SSTAGE 40960
#define SSMEM  (2*SSTAGE)
#define SNCHUNK 128

__global__ __launch_bounds__(256, 2) void scores_mma()
{
    extern __shared__ __align__(128) char smem[];
    const int b  = blockIdx.z;
    const int m0 = blockIdx.x * 128;
    const int n0 = blockIdx.y * 128;
    const int tid  = threadIdx.x;
    const int lane = tid & 31;
    const int wid  = tid >> 5;
    const int wm = (wid & 1) * 64;
    const int wn = (wid >> 1) * 32;
    const uint32_t sbase = smem_u32(smem);

    const size_t bo = (size_t)b * NSEQ * KCAT;
    const __nv_bfloat16* Ahi = gQc_hi + bo;
    const __nv_bfloat16* Alo = gQc_lo + bo;
    const __nv_bfloat16* Bhi = gKc_hi + bo;
    const __nv_bfloat16* Blo = gKc_lo + bo;

    float acc[4][4][4];
#pragma unroll
    for (int i = 0; i < 4; i++)
#pragma unroll
        for (int j = 0; j < 4; j++)
#pragma unroll
            for (int k = 0; k < 4; k++) acc[i][j][k] = 0.f;

    auto load_chunk = [&](int chunk, int s) {
        const int k0 = chunk * 32;
        const uint32_t sb = sbase + s * SSTAGE;
#pragma unroll
        for (int u = 0; u < 8; u++) {
            int idx = u * 256 + tid;
            int region = idx >> 9;
            int i2 = idx & 511;
            int r = i2 >> 2, c = i2 & 3;
            const __nv_bfloat16* base =
                (region == 0) ? Ahi : (region == 1) ? Alo
                              : (region == 2) ? Bhi : Blo;
            int row = ((region < 2) ? n0 : m0) + r;
            if (row > NSEQ - 1) row = NSEQ - 1;
            cp16(sb + region * 10240 + r * 80 + c * 16,
                 base + (size_t)row * KCAT + k0 + c * 8);
        }
    };

    load_chunk(0, 0);
    CP_COMMIT();

    const int lrow = (lane & 7) + ((lane >> 3) & 1) * 8;
    const int lcol = (lane >> 4) * 8;

    for (int it = 0; it < SNCHUNK; it++) {
        const int cur = it & 1;
        if (it + 1 < SNCHUNK) {
            load_chunk(it + 1, (it + 1) & 1);
            CP_COMMIT();
            CP_WAIT1();
        } else {
            CP_WAIT0();
        }
        __syncthreads();

        const uint32_t sb = sbase + cur * SSTAGE;
#pragma unroll
        for (int ks = 0; ks < 2; ks++) {
            const int colb = (ks * 16 + lcol) * 2;
            uint32_t Bh[4][2], Bl[4][2];
#pragma unroll
            for (int half = 0; half < 2; half++) {
                const int nrow = wn + half * 16 + lrow;
                uint32_t r0, r1, r2, r3;
                ldx4(sb + 20480 + nrow * 80 + colb, r0, r1, r2, r3);
                Bh[half * 2 + 0][0] = r0; Bh[half * 2 + 1][0] = r1;
                Bh[half * 2 + 0][1] = r2; Bh[half * 2 + 1][1] = r3;
                ldx4(sb + 30720 + nrow * 80 + colb, r0, r1, r2, r3);
                Bl[half * 2 + 0][0] = r0; Bl[half * 2 + 1][0] = r1;
                Bl[half * 2 + 0][1] = r2; Bl[half * 2 + 1][1] = r3;
            }
#pragma unroll
            for (int p = 0; p < 2; p++) {
                uint32_t ah[2][4], al[2][4];
#pragma unroll
                for (int m2 = 0; m2 < 2; m2++) {
                    const int mrow = wm + (p * 2 + m2) * 16 + lrow;
                    ldx4(sb + mrow * 80 + colb,
                         ah[m2][0], ah[m2][1], ah[m2][2], ah[m2][3]);
                    ldx4(sb + 10240 + mrow * 80 + colb,
                         al[m2][0], al[m2][1], al[m2][2], al[m2][3]);
                }
#pragma unroll
                for (int m2 = 0; m2 < 2; m2++)
#pragma unroll
                    for (int nj = 0; nj < 4; nj++)
                        mma16816(acc[p * 2 + m2][nj], ah[m2], Bh[nj]);
#pragma unroll
                for (int m2 = 0; m2 < 2; m2++)
#pragma unroll
                    for (int nj = 0; nj < 4; nj++)
                        mma16816(acc[p * 2 + m2][nj], ah[m2], Bl[nj]);
#pragma unroll
                for (int m2 = 0; m2 < 2; m2++)
#pragma unroll
                    for (int nj = 0; nj < 4; nj++)
                        mma16816(acc[p * 2 + m2][nj], al[m2], Bh[nj]);
            }
        }
        __syncthreads();
    }

    float* sc = g_scores + (size_t)b * NSEQ * NSEQ;
    const int gq = lane >> 2;
    const int tq = lane & 3;
#pragma unroll
    for (int mi = 0; mi < 4; mi++) {
#pragma unroll
        for (int nj = 0; nj < 4; nj++) {
            int col = m0 + wn + nj * 8 + tq * 2;
            if (col >= NSEQ) continue;
            int row0 = n0 + wm + mi * 16 + gq;
            if (row0 < NSEQ)
                *(float2*)(sc + (size_t)row0 * NSEQ + col) =
                    make_float2(acc[mi][nj][0], acc[mi][nj][1]);
            int row1 = row0 + 8;
            if (row1 < NSEQ)
                *(float2*)(sc + (size_t)row1 * NSEQ + col) =
                    make_float2(acc[mi][nj][2], acc[mi][nj][3]);
        }
    }
}

// ---------------- softmax -> bf16 hi/lo attn (padded to 224) --------------
__global__ __launch_bounds__(256) void softmax_kernel()
{
    const int row = blockIdx.x;
    float* s = g_scores + (size_t)row * NSEQ;
    const int tid = threadIdx.x;
    __shared__ float red[8];

    float v = (tid < NSEQ) ? s[tid] : -3.0e38f;
#pragma unroll
    for (int o = 16; o; o >>= 1) v = fmaxf(v, __shfl_xor_sync(0xffffffffu, v, o));
    if ((tid & 31) == 0) red[tid >> 5] = v;
    __syncthreads();
    float vmax = red[0];
#pragma unroll
    for (int w = 1; w < 8; w++) vmax = fmaxf(vmax, red[w]);

    const float scale = 0.02209708691207961f;
    float e = (tid < NSEQ) ? __expf((s[tid] - vmax) * scale) : 0.f;
    float sum = e;
#pragma unroll
    for (int o = 16; o; o >>= 1) sum += __shfl_xor_sync(0xffffffffu, sum, o);
    __syncthreads();
    if ((tid & 31) == 0) red[tid >> 5] = sum;
    __syncthreads();
    float tot = 0.f;
#pragma unroll
    for (int w = 0; w < 8; w++) tot += red[w];

    if (tid < KOUT) {
        float a = (tid < NSEQ) ? e / tot : 0.f;
        __nv_bfloat16 h, l;
        split_bf16(a, h, l);
        gAttn_hi[(size_t)row * KOUT + tid] = h;
        gAttn_lo[(size_t)row * KOUT + tid] = l;
    }
}

// ---------------- lv transpose + split: lvT[b][o][m] ----------------------
__global__ __launch_bounds__(256) void lvT_kernel()
{
    __shared__ float t[32][33];
    const int b  = blockIdx.z;
    const int o0 = blockIdx.x * 32;
    const int m0 = blockIdx.y * 32;
    const int tx = threadIdx.x, ty = threadIdx.y;
    const float* lv = g_lv + (size_t)b * NSEQ * HDIM;
#pragma unroll
    for (int r = ty; r < 32; r += 8) {
        int m = m0 + r;
        t[r][tx] = (m < NSEQ) ? lv[(size_t)m * HDIM + o0 + tx] : 0.f;
    }
    __syncthreads();
#pragma unroll
    for (int r = ty; r < 32; r += 8) {
        __nv_bfloat16 h, l;
        split_bf16(t[tx][r], h, l);
        size_t off = ((size_t)b * HDIM + o0 + r) * KOUT + m0 + tx;
        gLvT_hi[off] = h;
        gLvT_lo[off] = l;
    }
}

// =================== HMMA output GEMM ======================================
#define ONCHUNK 7

__global__ __launch_bounds__(256, 2) void out_mma(float* __restrict__ out)
{
    extern __shared__ __align__(128) char smem[];
    const int b  = blockIdx.z;
    const int o0 = blockIdx.x * 128;
    const int n0 = blockIdx.y * 128;
    const int tid  = threadIdx.x;
    const int lane = tid & 31;
    const int wid  = tid >> 5;
    const int wm = (wid & 1) * 64;
    const int wn = (wid >> 1) * 32;
    const uint32_t sbase = smem_u32(smem);

    const __nv_bfloat16* Ahi = gAttn_hi + (size_t)b * NSEQ * KOUT;
    const __nv_bfloat16* Alo = gAttn_lo + (size_t)b * NSEQ * KOUT;
    const __nv_bfloat16* Bhi = gLvT_hi + (size_t)b * HDIM * KOUT;
    const __nv_bfloat16* Blo = gLvT_lo + (size_t)b * HDIM * KOUT;

    float acc[4][4][4];
#pragma unroll
    for (int i = 0; i < 4; i++)
#pragma unroll
        for (int j = 0; j < 4; j++)
#pragma unroll
            for (int k = 0; k < 4; k++) acc[i][j][k] = 0.f;

    auto load_chunk = [&](int chunk, int s) {
        const int k0 = chunk * 32;
        const uint32_t sb = sbase + s * SSTAGE;
#pragma unroll
        for (int u = 0; u < 8; u++) {
            int idx = u * 256 + tid;
            int region = idx >> 9;
            int i2 = idx & 511;
            int r = i2 >> 2, c = i2 & 3;
            const __nv_bfloat16* base;
            size_t off;
            if (region < 2) {
                int row = n0 + r; if (row > NSEQ - 1) row = NSEQ - 1;
                base = region ? Alo : Ahi;
                off = (size_t)row * KOUT + k0 + c * 8;
            } else {
                base = (region == 3) ? Blo : Bhi;
                off = (size_t)(o0 + r) * KOUT + k0 + c * 8;
            }
            cp16(sb + region * 10240 + r * 80 + c * 16, base + off);
        }
    };

    load_chunk(0, 0);
    CP_COMMIT();

    const int lrow = (lane & 7) + ((lane >> 3) & 1) * 8;
    const int lcol = (lane >> 4) * 8;

    for (int it = 0; it < ONCHUNK; it++) {
        const int cur = it & 1;
        if (it + 1 < ONCHUNK) {
            load_chunk(it + 1, (it + 1) & 1);
            CP_COMMIT();
            CP_WAIT1();
        } else {
            CP_WAIT0();
        }
        __syncthreads();

        const uint32_t sb = sbase + cur * SSTAGE;
#pragma unroll
        for (int ks = 0; ks < 2; ks++) {
            const int colb = (ks * 16 + lcol) * 2;
            uint32_t Bh[4][2], Bl[4][2];
#pragma unroll
            for (int half = 0; half < 2; half++) {
                const int nrow = wn + half * 16 + lrow;
                uint32_t r0, r1, r2, r3;
                ldx4(sb + 20480 + nrow * 80 + colb, r0, r1, r2, r3);
                Bh[half * 2 + 0][0] = r0; Bh[half * 2 + 1][0] = r1;
                Bh[half * 2 + 0][1] = r2; Bh[half * 2 + 1][1] = r3;
                ldx4(sb + 30720 + nrow * 80 + colb, r0, r1, r2, r3);
                Bl[half * 2 + 0][0] = r0; Bl[half * 2 + 1][0] = r1;
                Bl[half * 2 + 0][1] = r2; Bl[half * 2 + 1][1] = r3;
            }
#pragma unroll
            for (int p = 0; p < 2; p++) {
                uint32_t ah[2][4], al[2][4];
#pragma unroll
                for (int m2 = 0; m2 < 2; m2++) {
                    const int mrow = wm + (p * 2 + m2) * 16 + lrow;
                    ldx4(sb + mrow * 80 + colb,
                         ah[m2][0], ah[m2][1], ah[m2][2], ah[m2][3]);
                    ldx4(sb + 10240 + mrow * 80 + colb,
                         al[m2][0], al[m2][1], al[m2][2], al[m2][3]);
                }
#pragma unroll
                for (int m2 = 0; m2 < 2; m2++)
#pragma unroll
                    for (int nj = 0; nj < 4; nj++)
                        mma16816(acc[p * 2 + m2][nj], ah[m2], Bh[nj]);
#pragma unroll
                for (int m2 = 0; m2 < 2; m2++)
#pragma unroll
                    for (int nj = 0; nj < 4; nj++)
                        mma16816(acc[p * 2 + m2][nj], ah[m2], Bl[nj]);
#pragma unroll
                for (int m2 = 0; m2 < 2; m2++)
#pragma unroll
                    for (int nj = 0; nj < 4; nj++)
                        mma16816(acc[p * 2 + m2][nj], al[m2], Bh[nj]);
            }
        }
        __syncthreads();
    }

    const int gq = lane >> 2;
    const int tq = lane & 3;
#pragma unroll
    for (int mi = 0; mi < 4; mi++) {
#pragma unroll
        for (int nj = 0; nj < 4; nj++) {
            int col = o0 + wn + nj * 8 + tq * 2;
            int row0 = n0 + wm + mi * 16 + gq;
            if (row0 < NSEQ)
                *(float2*)(out + ((size_t)b * NSEQ + row0) * HDIM + col) =
                    make_float2(acc[mi][nj][0], acc[mi][nj][1]);
            int row1 = row0 + 8;
            if (row1 < NSEQ)
                *(float2*)(out + ((size_t)b * NSEQ + row1) * HDIM + col) =
                    make_float2(acc[mi][nj][2], acc[mi][nj][3]);
        }
    }
}

// ---------------------------------------------------------------------------
extern "C" void kernel_launch(void* const* d_in, const int* in_sizes, int n_in,
                              void* d_out, int out_size)
{
    const float* input_query = (const float*)d_in[0];
    const float* input_key   = (const float*)d_in[1];
    const float* input_value = (const float*)d_in[2];
    const float* loc_vector  = (const float*)d_in[3];
    const float* Wq   = (const float*)d_in[4];
    const float* bq   = (const float*)d_in[5];
    const float* Wk   = (const float*)d_in[6];
    const float* bk   = (const float*)d_in[7];
    const float* Wv   = (const float*)d_in[8];
    const float* bv   = (const float*)d_in[9];
    const float* Wloc = (const float*)d_in[10];
    const float* bloc = (const float*)d_in[11];
    const float* Wlk  = (const float*)d_in[12];
    const float* blk  = (const float*)d_in[13];
    const float* param = (const float*)d_in[14];
    float* out = (float*)d_out;

    float *q1, *q2, *lk, *kloc, *lv, *At, *Wt;
    cudaGetSymbolAddress((void**)&q1,   g_q1);
    cudaGetSymbolAddress((void**)&q2,   g_q2);
    cudaGetSymbolAddress((void**)&lk,   g_lk);
    cudaGetSymbolAddress((void**)&kloc, g_kloc);
    cudaGetSymbolAddress((void**)&lv,   g_lv);
    cudaGetSymbolAddress((void**)&At,   gAt);
    cudaGetSymbolAddress((void**)&Wt,   gWt);

    cudaFuncSetAttribute(proj_mma, cudaFuncAttributeMaxDynamicSharedMemorySize,
                         TSMEM);
    cudaFuncSetAttribute(scores_mma, cudaFuncAttributeMaxDynamicSharedMemorySize,
                         SSMEM);
    cudaFuncSetAttribute(out_mma, cudaFuncAttributeMaxDynamicSharedMemorySize,
                         SSMEM);

    ConvAP CA;
    CA.src[0] = input_query; CA.src[1] = input_key;
    CA.src[2] = input_value; CA.src[3] = loc_vector;
    convA_kernel<<<dim3(MK / 1024, 1, 4), 256>>>(CA);

    ConvWP CW;
    CW.src[0] = Wq; CW.src[1] = Wloc; CW.src[2] = Wk; CW.src[3] = Wlk; CW.src[4] = Wv;
    convW_kernel<<<dim3(HDIM / 32, DDIM / 32, 5), dim3(32, 8)>>>(CW);

    ProjParams P;
    const int aidx[5] = {0, 3, 1, 3, 2};     // query, loc, key, loc, value
    const float* biases[5] = {bq, bloc, bk, blk, bv};
    float* outs[5] = {q1, q2, lk, kloc, lv};
    for (int g = 0; g < 5; g++) {
        P.A[g]    = At + (size_t)aidx[g] * MK;
        P.B[g]    = Wt + (size_t)g * KN;
        P.bias[g] = biases[g];
        P.C[g]    = outs[g];
    }
    proj_mma<<<dim3(HDIM / 128, MTOT / 128, 5), 256, TSMEM>>>(P);

    qkpack_kernel<<<(BATCH * NSEQ * HDIM / 2 + 255) / 256, 256>>>(param);
    lvT_kernel<<<dim3(HDIM / 32, KOUT / 32, BATCH), dim3(32, 8)>>>();

    scores_mma<<<dim3(2, 2, BATCH), 256, SSMEM>>>();
    softmax_kernel<<<BATCH * NSEQ, 256>>>();
    out_mma<<<dim3(HDIM / 128, 2, BATCH), 256, SSMEM>>>(out);
}

// round 8
// speedup vs baseline: 3.7102x; 1.1851x over previous
#include <cuda_runtime.h>
#include <cuda_bf16.h>
#include <math.h>
#include <stdint.h>

#define BATCH 16
#define NSEQ  200
#define DDIM  2048
#define HDIM  2048
#define MTOT  (BATCH*NSEQ)          // 3200
#define MK    (MTOT*DDIM)
#define KN    (DDIM*HDIM)
#define KCAT  4096                  // scores concatenated K
#define KOUT  224                   // out GEMM K (200 padded)

// ---------------- scratch (device globals) ---------------------------------
__device__ float g_q1[BATCH*NSEQ*HDIM];
__device__ float g_q2[BATCH*NSEQ*HDIM];
__device__ float g_lk[BATCH*NSEQ*HDIM];
__device__ float g_kloc[BATCH*NSEQ*HDIM];
__device__ float g_lv[BATCH*NSEQ*HDIM];
__device__ float g_scores[BATCH*NSEQ*NSEQ];

// fragment-packed tf32 operands.
// A: per matrix, [T=200 m-tiles][c=64 chunks][ks=4][lane=32][v=4] floats
//    v: (gq,tq),(gq+8,tq),(gq,tq+4),(gq+8,tq+4)
__device__ __align__(16) float gAt[4*MK];
// W: per matrix, [T8=256 n-tiles][c=64][ks=4][lane=32][v=2] floats
//    v: (n=T8*8+gq, k=c*32+ks*8+tq), (.., k+4)
__device__ __align__(16) float gWt[5*KN];

// scores/out bf16-split operands
__device__ __align__(16) __nv_bfloat16 gQc_hi[BATCH*NSEQ*KCAT];
__device__ __align__(16) __nv_bfloat16 gQc_lo[BATCH*NSEQ*KCAT];
__device__ __align__(16) __nv_bfloat16 gKc_hi[BATCH*NSEQ*KCAT];
__device__ __align__(16) __nv_bfloat16 gKc_lo[BATCH*NSEQ*KCAT];
__device__ __align__(16) __nv_bfloat16 gAttn_hi[BATCH*NSEQ*KOUT];
__device__ __align__(16) __nv_bfloat16 gAttn_lo[BATCH*NSEQ*KOUT];
__device__ __align__(16) __nv_bfloat16 gLvT_hi[BATCH*HDIM*KOUT];
__device__ __align__(16) __nv_bfloat16 gLvT_lo[BATCH*HDIM*KOUT];

// ============================ helpers ======================================
__device__ __forceinline__ uint32_t smem_u32(const void* p) {
    uint32_t a;
    asm("{ .reg .u64 t; cvta.to.shared.u64 t, %1; cvt.u32.u64 %0, t; }"
        : "=r"(a) : "l"(p));
    return a;
}
__device__ __forceinline__ void cp16(uint32_t dst, const void* src) {
    asm volatile("cp.async.cg.shared.global [%0], [%1], 16;" :: "r"(dst), "l"(src));
}
#define CP_COMMIT() asm volatile("cp.async.commit_group;" ::: "memory")
#define CP_WAIT1()  asm volatile("cp.async.wait_group 1;" ::: "memory")
#define CP_WAIT0()  asm volatile("cp.async.wait_group 0;" ::: "memory")

__device__ __forceinline__ void ldx4(uint32_t addr, uint32_t& r0, uint32_t& r1,
                                     uint32_t& r2, uint32_t& r3) {
    asm volatile("ldmatrix.sync.aligned.m8n8.x4.shared.b16 {%0,%1,%2,%3}, [%4];"
                 : "=r"(r0), "=r"(r1), "=r"(r2), "=r"(r3) : "r"(addr));
}
__device__ __forceinline__ void mma16816(float* c, const uint32_t* a,
                                         const uint32_t* b) {
    asm volatile(
        "mma.sync.aligned.m16n8k16.row.col.f32.bf16.bf16.f32 "
        "{%0,%1,%2,%3}, {%4,%5,%6,%7}, {%8,%9}, {%0,%1,%2,%3};"
        : "+f"(c[0]), "+f"(c[1]), "+f"(c[2]), "+f"(c[3])
        : "r"(a[0]), "r"(a[1]), "r"(a[2]), "r"(a[3]), "r"(b[0]), "r"(b[1]));
}
__device__ __forceinline__ void mma_tf32(float* c, const float4 a,
                                         const float2 b) {
    asm volatile(
        "mma.sync.aligned.m16n8k8.row.col.f32.tf32.tf32.f32 "
        "{%0,%1,%2,%3}, {%4,%5,%6,%7}, {%8,%9}, {%0,%1,%2,%3};"
        : "+f"(c[0]), "+f"(c[1]), "+f"(c[2]), "+f"(c[3])
        : "r"(__float_as_uint(a.x)), "r"(__float_as_uint(a.y)),
          "r"(__float_as_uint(a.z)), "r"(__float_as_uint(a.w)),
          "r"(__float_as_uint(b.x)), "r"(__float_as_uint(b.y)));
}
__device__ __forceinline__ float f2tf32(float x) {
    uint32_t r;
    asm("cvt.rna.tf32.f32 %0, %1;" : "=r"(r) : "f"(x));
    return __uint_as_float(r);
}
__device__ __forceinline__ void split_bf16(float x, __nv_bfloat16& h,
                                           __nv_bfloat16& l) {
    h = __float2bfloat16_rn(x);
    l = __float2bfloat16_rn(x - __bfloat162float(h));
}

// =================== conversion kernels (fragment packing) =================
// A: grid (200, 32, 4), 256 thr. Each thread emits one float4 fragment group.
struct ConvAP { const float* src[4]; };
__global__ __launch_bounds__(256) void convA_kernel(ConvAP P)
{
    const int mat = blockIdx.z;
    const int T   = blockIdx.x;
    const int t   = threadIdx.x;
    const int c   = blockIdx.y * 2 + (t >> 7);
    const int g   = t & 127;
    const int ks  = g >> 5;
    const int lane = g & 31;
    const int gq = lane >> 2, tq = lane & 3;
    const float* src = P.src[mat];

    const size_t row0 = (size_t)(T * 16 + gq) * DDIM;
    const int col0 = c * 32 + ks * 8 + tq;
    float4 v;
    v.x = f2tf32(src[row0 + col0]);
    v.y = f2tf32(src[row0 + 8 * DDIM + col0]);
    v.z = f2tf32(src[row0 + col0 + 4]);
    v.w = f2tf32(src[row0 + 8 * DDIM + col0 + 4]);
    *(float4*)(gAt + (size_t)mat * MK +
               ((size_t)(T * 64 + c) * 4 + ks) * 128 + lane * 4) = v;
}

// W: grid (256, 32, 5), 256 thr. Each thread emits one float2 fragment pair.
struct ConvWP { const float* src[5]; };
__global__ __launch_bounds__(256) void convW_kernel(ConvWP P)
{
    const int w  = blockIdx.z;
    const int T8 = blockIdx.x;
    const int t  = threadIdx.x;
    const int c  = blockIdx.y * 2 + (t >> 7);
    const int g  = t & 127;
    const int ks = g >> 5;
    const int lane = g & 31;
    const int gq = lane >> 2, tq = lane & 3;
    const float* W = P.src[w];

    const int n  = T8 * 8 + gq;
    const int k0 = c * 32 + ks * 8 + tq;
    float2 v;
    v.x = f2tf32(W[(size_t)k0 * HDIM + n]);
    v.y = f2tf32(W[(size_t)(k0 + 4) * HDIM + n]);
    *(float2*)(gWt + (size_t)w * KN +
               ((size_t)(T8 * 64 + c) * 4 + ks) * 64 + lane * 2) = v;
}

// =================== TF32 projection GEMM ==================================
// C[3200,2048] = A @ Wt^T + bias.  BM=128 x BN=128, BK=32, 256 thr (2x4 warps),
// warp tile 64x32.  Fragment-packed smem, 3-stage cp.async, 1 sync/chunk.
struct ProjParams {
    const float *A[5], *B[5], *bias[5];
    float* C[5];
};

#define TSTAGEB 32768                // A 16KB + B 16KB
#define TSTAGEF 8192                 // floats
#define TSMEM   (3*TSTAGEB)          // 98304 -> 2 CTAs/SM
#define NCHUNK  64

__global__ __launch_bounds__(256, 2) void proj_mma(ProjParams P)
{
    extern __shared__ __align__(128) char smem[];
    const int g  = blockIdx.z;
    const int bn = blockIdx.x * 128;
    const int bm = blockIdx.y * 128;
    const int tid  = threadIdx.x;
    const int lane = tid & 31;
    const int wid  = tid >> 5;
    const int wm = (wid & 1) * 64;
    const int wn = (wid >> 1) * 32;
    const int wm16 = (wm >> 4);        // 0 or 4
    const int wn8  = (wn >> 3);        // 0,4,8,12
    const uint32_t sbase = smem_u32(smem);
    float* fs = reinterpret_cast<float*>(smem);

    const float* A = P.A[g];           // packed
    const float* B = P.B[g];           // packed
    const float* bias = P.bias[g];
    float* C = P.C[g];

    const int T0  = blockIdx.y * 8;    // first m-tile
    const int NT0 = blockIdx.x * 16;   // first n-tile

    float acc[4][4][4];
#pragma unroll
    for (int i = 0; i < 4; i++)
#pragma unroll
        for (int j = 0; j < 4; j++)
#pragma unroll
            for (int k = 0; k < 4; k++) acc[i][j][k] = 0.f;

    // 2048 cp16 per chunk (A 1024 + B 1024) -> 8 per thread, fully contiguous
    auto load_chunk = [&](int c, int s) {
        const uint32_t sb = sbase + s * TSTAGEB;
#pragma unroll
        for (int u = 0; u < 8; u++) {
            int idx = u * 256 + tid;
            if (idx < 1024) {                  // A: 8 tiles x 128 cp16
                int t = idx >> 7, w = idx & 127;
                cp16(sb + (t * 512 + w * 4) * 4,
                     A + ((size_t)(T0 + t) * 64 + c) * 512 + w * 4);
            } else {                           // B: 16 tiles x 64 cp16
                int j = idx - 1024;
                int nt = j >> 6, w = j & 63;
                cp16(sb + 16384 + (nt * 256 + w * 4) * 4,
                     B + ((size_t)(NT0 + nt) * 64 + c) * 256 + w * 4);
            }
        }
    };

    load_chunk(0, 0); CP_COMMIT();
    load_chunk(1, 1); CP_COMMIT();

    for (int it = 0; it < NCHUNK; it++) {
        const int cur = it % 3;
        if (it == NCHUNK - 1) { CP_WAIT0(); } else { CP_WAIT1(); }
        __syncthreads();
        if (it + 2 < NCHUNK) {
            load_chunk(it + 2, (it + 2) % 3);
            CP_COMMIT();
        }

        const float* As = fs + cur * TSTAGEF;
        const float* Bs = As + 4096;
#pragma unroll
        for (int ks = 0; ks < 4; ks++) {
            float2 bfr[4];
#pragma unroll
            for (int nj = 0; nj < 4; nj++)
                bfr[nj] = *(const float2*)(Bs + ((wn8 + nj) * 4 + ks) * 64 + lane * 2);
#pragma unroll
            for (int mi = 0; mi < 4; mi++) {
                float4 afr = *(const float4*)(As + ((wm16 + mi) * 4 + ks) * 128 + lane * 4);
#pragma unroll
                for (int nj = 0; nj < 4; nj++)
                    mma_tf32(acc[mi][nj], afr, bfr[nj]);
            }
        }
    }

    const int gq = lane >> 2;
    const int tq = lane & 3;
#pragma unroll
    for (int mi = 0; mi < 4; mi++) {
#pragma unroll
        for (int nj = 0; nj < 4; nj++) {
            int col = bn + wn + nj * 8 + tq * 2;
            float b0 = __ldg(bias + col);
            float b1 = __ldg(bias + col + 1);
            int row0 = bm + wm + mi * 16 + gq;
            *(float2*)(C + (size_t)row0 * HDIM + col) =
                make_float2(acc[mi][nj][0] + b0, acc[mi][nj][1] + b1);
            *(float2*)(C + (size_t)(row0 + 8) * HDIM + col) =
                make_float2(acc[mi][nj][2] + b0, acc[mi][nj][3] + b1);
        }
    }
}

// =============== qk pack: build concat bf16 hi/lo operands =================
__global__ __launch_bounds__(256) void qkpack_kernel(const float* __restrict__ param)
{
    size_t i2 = (size_t)blockIdx.x * 256 + threadIdx.x;
    if (i2 >= (size_t)BATCH * NSEQ * HDIM / 2) return;
    size_t i = i2 * 2;
    size_t bn = i / HDIM;
    int    h  = (int)(i % HDIM);
    size_t base = bn * KCAT + h;

    float2 lq = *(const float2*)(g_q1 + i);
    float2 ll = *(const float2*)(g_q2 + i);
    float2 pp = *(const float2*)(param + i);
    float2 lk = *(const float2*)(g_lk + i);
    float2 kl = *(const float2*)(g_kloc + i);

    __nv_bfloat16 h0, l0, h1, l1;
    split_bf16(lq.x + pp.x, h0, l0); split_bf16(lq.y + pp.y, h1, l1);
    *(__nv_bfloat162*)(gQc_hi + base) = __nv_bfloat162(h0, h1);
    *(__nv_bfloat162*)(gQc_lo + base) = __nv_bfloat162(l0, l1);
    split_bf16(lq.x + ll.x, h0, l0); split_bf16(lq.y + ll.y, h1, l1);
    *(__nv_bfloat162*)(gQc_hi + base + DDIM) = __nv_bfloat162(h0, h1);
    *(__nv_bfloat162*)(gQc_lo + base + DDIM) = __nv_bfloat162(l0, l1);
    split_bf16(lk.x, h0, l0); split_bf16(lk.y, h1, l1);
    *(__nv_bfloat162*)(gKc_hi + base) = __nv_bfloat162(h0, h1);
    *(__nv_bfloat162*)(gKc_lo + base) = __nv_bfloat162(l0, l1);
    split_bf16(kl.x, h0, l0); split_bf16(kl.y, h1, l1);
    *(__nv_bfloat162*)(gKc_hi + base + DDIM) = __nv_bfloat162(h0, h1);
    *(__nv_bfloat162*)(gKc_lo + base + DDIM) = __nv_bfloat162(l0, l1);
}

// =================== HMMA scores GEMM ======================================
#define SSTAGE 40960
#define SSMEM  (2*SSTAGE)
#define SNCHUNK 128

__global__ __launch_bounds__(256, 2) void scores_mma()
{
    extern __shared__ __align__(128) char smem[];
    const int b  = blockIdx.z;
    const int m0 = blockIdx.x * 128;
    const int n0 = blockIdx.y * 128;
    const int tid  = threadIdx.x;
    const int lane = tid & 31;
    const int wid  = tid >> 5;
    const int wm = (wid & 1) * 64;
    const int wn = (wid >> 1) * 32;
    const uint32_t sbase = smem_u32(smem);

    const size_t bo = (size_t)b * NSEQ * KCAT;
    const __nv_bfloat16* Ahi = gQc_hi + bo;
    const __nv_bfloat16* Alo = gQc_lo + bo;
    const __nv_bfloat16* Bhi = gKc_hi + bo;
    const __nv_bfloat16* Blo = gKc_lo + bo;

    float acc[4][4][4];
#pragma unroll
    for (int i = 0; i < 4; i++)
#pragma unroll
        for (int j = 0; j < 4; j++)
#pragma unroll
            for (int k = 0; k < 4; k++) acc[i][j][k] = 0.f;

    auto load_chunk = [&](int chunk, int s) {
        const int k0 = chunk * 32;
        const uint32_t sb = sbase + s * SSTAGE;
#pragma unroll
        for (int u = 0; u < 8; u++) {
            int idx = u * 256 + tid;
            int region = idx >> 9;
            int i2 = idx & 511;
            int r = i2 >> 2, c = i2 & 3;
            const __nv_bfloat16* base =
                (region == 0) ? Ahi : (region == 1) ? Alo
                              : (region == 2) ? Bhi : Blo;
            int row = ((region < 2) ? n0 : m0) + r;
            if (row > NSEQ - 1) row = NSEQ - 1;
            cp16(sb + region * 10240 + r * 80 + c * 16,
                 base + (size_t)row * KCAT + k0 + c * 8);
        }
    };

    load_chunk(0, 0);
    CP_COMMIT();

    const int lrow = (lane & 7) + ((lane >> 3) & 1) * 8;
    const int lcol = (lane >> 4) * 8;

    for (int it = 0; it < SNCHUNK; it++) {
        const int cur = it & 1;
        if (it + 1 < SNCHUNK) {
            load_chunk(it + 1, (it + 1) & 1);
            CP_COMMIT();
            CP_WAIT1();
        } else {
            CP_WAIT0();
        }
        __syncthreads();

        const uint32_t sb = sbase + cur * SSTAGE;
#pragma unroll
        for (int ks = 0; ks < 2; ks++) {
            const int colb = (ks * 16 + lcol) * 2;
            uint32_t Bh[4][2], Bl[4][2];
#pragma unroll
            for (int half = 0; half < 2; half++) {
                const int nrow = wn + half * 16 + lrow;
                uint32_t r0, r1, r2, r3;
                ldx4(sb + 20480 + nrow * 80 + colb, r0, r1, r2, r3);
                Bh[half * 2 + 0][0] = r0; Bh[half * 2 + 1][0] = r1;
                Bh[half * 2 + 0][1] = r2; Bh[half * 2 + 1][1] = r3;
                ldx4(sb + 30720 + nrow * 80 + colb, r0, r1, r2, r3);
                Bl[half * 2 + 0][0] = r0; Bl[half * 2 + 1][0] = r1;
                Bl[half * 2 + 0][1] = r2; Bl[half * 2 + 1][1] = r3;
            }
#pragma unroll
            for (int p = 0; p < 2; p++) {
                uint32_t ah[2][4], al[2][4];
#pragma unroll
                for (int m2 = 0; m2 < 2; m2++) {
                    const int mrow = wm + (p * 2 + m2) * 16 + lrow;
                    ldx4(sb + mrow * 80 + colb,
                         ah[m2][0], ah[m2][1], ah[m2][2], ah[m2][3]);
                    ldx4(sb + 10240 + mrow * 80 + colb,
                         al[m2][0], al[m2][1], al[m2][2], al[m2][3]);
                }
#pragma unroll
                for (int m2 = 0; m2 < 2; m2++)
#pragma unroll
                    for (int nj = 0; nj < 4; nj++)
                        mma16816(acc[p * 2 + m2][nj], ah[m2], Bh[nj]);
#pragma unroll
                for (int m2 = 0; m2 < 2; m2++)
#pragma unroll
                    for (int nj = 0; nj < 4; nj++)
                        mma16816(acc[p * 2 + m2][nj], ah[m2], Bl[nj]);
#pragma unroll
                for (int m2 = 0; m2 < 2; m2++)
#pragma unroll
                    for (int nj = 0; nj < 4; nj++)
                        mma16816(acc[p * 2 + m2][nj], al[m2], Bh[nj]);
            }
        }
        __syncthreads();
    }

    float* sc = g_scores + (size_t)b * NSEQ * NSEQ;
    const int gq = lane >> 2;
    const int tq = lane & 3;
#pragma unroll
    for (int mi = 0; mi < 4; mi++) {
#pragma unroll
        for (int nj = 0; nj < 4; nj++) {
            int col = m0 + wn + nj * 8 + tq * 2;
            if (col >= NSEQ) continue;
            int row0 = n0 + wm + mi * 16 + gq;
            if (row0 < NSEQ)
                *(float2*)(sc + (size_t)row0 * NSEQ + col) =
                    make_float2(acc[mi][nj][0], acc[mi][nj][1]);
            int row1 = row0 + 8;
            if (row1 < NSEQ)
                *(float2*)(sc + (size_t)row1 * NSEQ + col) =
                    make_float2(acc[mi][nj][2], acc[mi][nj][3]);
        }
    }
}

// ---------------- softmax -> bf16 hi/lo attn (padded to 224) --------------
__global__ __launch_bounds__(256) void softmax_kernel()
{
    const int row = blockIdx.x;
    float* s = g_scores + (size_t)row * NSEQ;
    const int tid = threadIdx.x;
    __shared__ float red[8];

    float v = (tid < NSEQ) ? s[tid] : -3.0e38f;
#pragma unroll
    for (int o = 16; o; o >>= 1) v = fmaxf(v, __shfl_xor_sync(0xffffffffu, v, o));
    if ((tid & 31) == 0) red[tid >> 5] = v;
    __syncthreads();
    float vmax = red[0];
#pragma unroll
    for (int w = 1; w < 8; w++) vmax = fmaxf(vmax, red[w]);

    const float scale = 0.02209708691207961f;
    float e = (tid < NSEQ) ? __expf((s[tid] - vmax) * scale) : 0.f;
    float sum = e;
#pragma unroll
    for (int o = 16; o; o >>= 1) sum += __shfl_xor_sync(0xffffffffu, sum, o);
    __syncthreads();
    if ((tid & 31) == 0) red[tid >> 5] = sum;
    __syncthreads();
    float tot = 0.f;
#pragma unroll
    for (int w = 0; w < 8; w++) tot += red[w];

    if (tid < KOUT) {
        float a = (tid < NSEQ) ? e / tot : 0.f;
        __nv_bfloat16 h, l;
        split_bf16(a, h, l);
        gAttn_hi[(size_t)row * KOUT + tid] = h;
        gAttn_lo[(size_t)row * KOUT + tid] = l;
    }
}

// ---------------- lv transpose + split: lvT[b][o][m] ----------------------
__global__ __launch_bounds__(256) void lvT_kernel()
{
    __shared__ float t[32][33];
    const int b  = blockIdx.z;
    const int o0 = blockIdx.x * 32;
    const int m0 = blockIdx.y * 32;
    const int tx = threadIdx.x, ty = threadIdx.y;
    const float* lv = g_lv + (size_t)b * NSEQ * HDIM;
#pragma unroll
    for (int r = ty; r < 32; r += 8) {
        int m = m0 + r;
        t[r][tx] = (m < NSEQ) ? lv[(size_t)m * HDIM + o0 + tx] : 0.f;
    }
    __syncthreads();
#pragma unroll
    for (int r = ty; r < 32; r += 8) {
        __nv_bfloat16 h, l;
        split_bf16(t[tx][r], h, l);
        size_t off = ((size_t)b * HDIM + o0 + r) * KOUT + m0 + tx;
        gLvT_hi[off] = h;
        gLvT_lo[off] = l;
    }
}

// =================== HMMA output GEMM ======================================
#define ONCHUNK 7

__global__ __launch_bounds__(256, 2) void out_mma(float* __restrict__ out)
{
    extern __shared__ __align__(128) char smem[];
    const int b  = blockIdx.z;
    const int o0 = blockIdx.x * 128;
    const int n0 = blockIdx.y * 128;
    const int tid  = threadIdx.x;
    const int lane = tid & 31;
    const int wid  = tid >> 5;
    const int wm = (wid & 1) * 64;
    const int wn = (wid >> 1) * 32;
    const uint32_t sbase = smem_u32(smem);

    const __nv_bfloat16* Ahi = gAttn_hi + (size_t)b * NSEQ * KOUT;
    const __nv_bfloat16* Alo = gAttn_lo + (size_t)b * NSEQ * KOUT;
    const __nv_bfloat16* Bhi = gLvT_hi + (size_t)b * HDIM * KOUT;
    const __nv_bfloat16* Blo = gLvT_lo + (size_t)b * HDIM * KOUT;

    float acc[4][4][4];
#pragma unroll
    for (int i = 0; i < 4; i++)
#pragma unroll
        for (int j = 0; j < 4; j++)
#pragma unroll
            for (int k = 0; k < 4; k++) acc[i][j][k] = 0.f;

    auto load_chunk = [&](int chunk, int s) {
        const int k0 = chunk * 32;
        const uint32_t sb = sbase + s * SSTAGE;
#pragma unroll
        for (int u = 0; u < 8; u++) {
            int idx = u * 256 + tid;
            int region = idx >> 9;
            int i2 = idx & 511;
            int r = i2 >> 2, c = i2 & 3;
            const __nv_bfloat16* base;
            size_t off;
            if (region < 2) {
                int row = n0 + r; if (row > NSEQ - 1) row = NSEQ - 1;
                base = region ? Alo : Ahi;
                off = (size_t)row * KOUT + k0 + c * 8;
            } else {
                base = (region == 3) ? Blo : Bhi;
                off = (size_t)(o0 + r) * KOUT + k0 + c * 8;
            }
            cp16(sb + region * 10240 + r * 80 + c * 16, base + off);
        }
    };

    load_chunk(0, 0);
    CP_COMMIT();

    const int lrow = (lane & 7) + ((lane >> 3) & 1) * 8;
    const int lcol = (lane >> 4) * 8;

    for (int it = 0; it < ONCHUNK; it++) {
        const int cur = it & 1;
        if (it + 1 < ONCHUNK) {
            load_chunk(it + 1, (it + 1) & 1);
            CP_COMMIT();
            CP_WAIT1();
        } else {
            CP_WAIT0();
        }
        __syncthreads();

        const uint32_t sb = sbase + cur * SSTAGE;
#pragma unroll
        for (int ks = 0; ks < 2; ks++) {
            const int colb = (ks * 16 + lcol) * 2;
            uint32_t Bh[4][2], Bl[4][2];
#pragma unroll
            for (int half = 0; half < 2; half++) {
                const int nrow = wn + half * 16 + lrow;
                uint32_t r0, r1, r2, r3;
                ldx4(sb + 20480 + nrow * 80 + colb, r0, r1, r2, r3);
                Bh[half * 2 + 0][0] = r0; Bh[half * 2 + 1][0] = r1;
                Bh[half * 2 + 0][1] = r2; Bh[half * 2 + 1][1] = r3;
                ldx4(sb + 30720 + nrow * 80 + colb, r0, r1, r2, r3);
                Bl[half * 2 + 0][0] = r0; Bl[half * 2 + 1][0] = r1;
                Bl[half * 2 + 0][1] = r2; Bl[half * 2 + 1][1] = r3;
            }
#pragma unroll
            for (int p = 0; p < 2; p++) {
                uint32_t ah[2][4], al[2][4];
#pragma unroll
                for (int m2 = 0; m2 < 2; m2++) {
                    const int mrow = wm + (p * 2 + m2) * 16 + lrow;
                    ldx4(sb + mrow * 80 + colb,
                         ah[m2][0], ah[m2][1], ah[m2][2], ah[m2][3]);
                    ldx4(sb + 10240 + mrow * 80 + colb,
                         al[m2][0], al[m2][1], al[m2][2], al[m2][3]);
                }
#pragma unroll
                for (int m2 = 0; m2 < 2; m2++)
#pragma unroll
                    for (int nj = 0; nj < 4; nj++)
                        mma16816(acc[p * 2 + m2][nj], ah[m2], Bh[nj]);
#pragma unroll
                for (int m2 = 0; m2 < 2; m2++)
#pragma unroll
                    for (int nj = 0; nj < 4; nj++)
                        mma16816(acc[p * 2 + m2][nj], ah[m2], Bl[nj]);
#pragma unroll
                for (int m2 = 0; m2 < 2; m2++)
#pragma unroll
                    for (int nj = 0; nj < 4; nj++)
                        mma16816(acc[p * 2 + m2][nj], al[m2], Bh[nj]);
            }
        }
        __syncthreads();
    }

    const int gq = lane >> 2;
    const int tq = lane & 3;
#pragma unroll
    for (int mi = 0; mi < 4; mi++) {
#pragma unroll
        for (int nj = 0; nj < 4; nj++) {
            int col = o0 + wn + nj * 8 + tq * 2;
            int row0 = n0 + wm + mi * 16 + gq;
            if (row0 < NSEQ)
                *(float2*)(out + ((size_t)b * NSEQ + row0) * HDIM + col) =
                    make_float2(acc[mi][nj][0], acc[mi][nj][1]);
            int row1 = row0 + 8;
            if (row1 < NSEQ)
                *(float2*)(out + ((size_t)b * NSEQ + row1) * HDIM + col) =
                    make_float2(acc[mi][nj][2], acc[mi][nj][3]);
        }
    }
}

// ---------------------------------------------------------------------------
extern "C" void kernel_launch(void* const* d_in, const int* in_sizes, int n_in,
                              void* d_out, int out_size)
{
    const float* input_query = (const float*)d_in[0];
    const float* input_key   = (const float*)d_in[1];
    const float* input_value = (const float*)d_in[2];
    const float* loc_vector  = (const float*)d_in[3];
    const float* Wq   = (const float*)d_in[4];
    const float* bq   = (const float*)d_in[5];
    const float* Wk   = (const float*)d_in[6];
    const float* bk   = (const float*)d_in[7];
    const float* Wv   = (const float*)d_in[8];
    const float* bv   = (const float*)d_in[9];
    const float* Wloc = (const float*)d_in[10];
    const float* bloc = (const float*)d_in[11];
    const float* Wlk  = (const float*)d_in[12];
    const float* blk  = (const float*)d_in[13];
    const float* param = (const float*)d_in[14];
    float* out = (float*)d_out;

    float *q1, *q2, *lk, *kloc, *lv, *At, *Wt;
    cudaGetSymbolAddress((void**)&q1,   g_q1);
    cudaGetSymbolAddress((void**)&q2,   g_q2);
    cudaGetSymbolAddress((void**)&lk,   g_lk);
    cudaGetSymbolAddress((void**)&kloc, g_kloc);
    cudaGetSymbolAddress((void**)&lv,   g_lv);
    cudaGetSymbolAddress((void**)&At,   gAt);
    cudaGetSymbolAddress((void**)&Wt,   gWt);

    cudaFuncSetAttribute(proj_mma, cudaFuncAttributeMaxDynamicSharedMemorySize,
                         TSMEM);
    cudaFuncSetAttribute(scores_mma, cudaFuncAttributeMaxDynamicSharedMemorySize,
                         SSMEM);
    cudaFuncSetAttribute(out_mma, cudaFuncAttributeMaxDynamicSharedMemorySize,
                         SSMEM);

    ConvAP CA;
    CA.src[0] = input_query; CA.src[1] = input_key;
    CA.src[2] = input_value; CA.src[3] = loc_vector;
    convA_kernel<<<dim3(200, 32, 4), 256>>>(CA);

    ConvWP CW;
    CW.src[0] = Wq; CW.src[1] = Wloc; CW.src[2] = Wk; CW.src[3] = Wlk; CW.src[4] = Wv;
    convW_kernel<<<dim3(256, 32, 5), 256>>>(CW);

    ProjParams P;
    const int aidx[5] = {0, 3, 1, 3, 2};     // query, loc, key, loc, value
    const float* biases[5] = {bq, bloc, bk, blk, bv};
    float* outs[5] = {q1, q2, lk, kloc, lv};
    for (int g = 0; g < 5; g++) {
        P.A[g]    = At + (size_t)aidx[g] * MK;
        P.B[g]    = Wt + (size_t)g * KN;
        P.bias[g] = biases[g];
        P.C[g]    = outs[g];
    }
    proj_mma<<<dim3(HDIM / 128, MTOT / 128, 5), 256, TSMEM>>>(P);

    qkpack_kernel<<<(BATCH * NSEQ * HDIM / 2 + 255) / 256, 256>>>(param);
    lvT_kernel<<<dim3(HDIM / 32, KOUT / 32, BATCH), dim3(32, 8)>>>();

    scores_mma<<<dim3(2, 2, BATCH), 256, SSMEM>>>();
    softmax_kernel<<<BATCH * NSEQ, 256>>>();
    out_mma<<<dim3(HDIM / 128, 2, BATCH), 256, SSMEM>>>(out);
}